// round 8
// baseline (speedup 1.0000x reference)
#include <cuda_runtime.h>
#include <cuda_bf16.h>
#include <math.h>
#include <stdint.h>

#define BATCH 16
#define N1D 1024
#define CCH 256

// ---------------- device scratch ----------------
__device__ float g_p1[BATCH * N1D * CCH];
__device__ float g_x3[BATCH * 64 * CCH];
__device__ float g_att2[BATCH * 256 * 256];
__device__ float g_att3[BATCH * 64 * 64];
__device__ __nv_bfloat16 g_x1h[BATCH * N1D * CCH];
__device__ __nv_bfloat16 g_x1l[BATCH * N1D * CCH];
__device__ __nv_bfloat16 g_x2h[BATCH * 256 * CCH];
__device__ __nv_bfloat16 g_x2l[BATCH * 256 * CCH];
__device__ __nv_bfloat16 g_f1h[BATCH * N1D * CCH];
__device__ __nv_bfloat16 g_f1l[BATCH * N1D * CCH];
__device__ __nv_bfloat16 g_f2h[BATCH * 256 * 512];
__device__ __nv_bfloat16 g_f2l[BATCH * 256 * 512];
__device__ __nv_bfloat16 g_f3h[BATCH * 64 * 1024];
__device__ __nv_bfloat16 g_f3l[BATCH * 64 * 1024];
__device__ __nv_bfloat16 g_w1h[256 * 256],  g_w1l[256 * 256];
__device__ __nv_bfloat16 g_w2h[512 * 256],  g_w2l[512 * 256];
__device__ __nv_bfloat16 g_w3h[1024 * 256], g_w3l[1024 * 256];

// ---------------- warp-MMA helpers ----------------
__device__ __forceinline__ uint32_t smem_u32(const void* p) {
    uint32_t a;
    asm("{ .reg .u64 t; cvta.to.shared.u64 t, %1; cvt.u32.u64 %0, t; }"
        : "=r"(a) : "l"(p));
    return a;
}
__device__ __forceinline__ void ldsm4(uint32_t* r, uint32_t a) {
    asm volatile("ldmatrix.sync.aligned.m8n8.x4.shared.b16 {%0,%1,%2,%3}, [%4];"
        : "=r"(r[0]), "=r"(r[1]), "=r"(r[2]), "=r"(r[3]) : "r"(a));
}
__device__ __forceinline__ void ldsm4t(uint32_t* r, uint32_t a) {
    asm volatile("ldmatrix.sync.aligned.m8n8.x4.trans.shared.b16 {%0,%1,%2,%3}, [%4];"
        : "=r"(r[0]), "=r"(r[1]), "=r"(r[2]), "=r"(r[3]) : "r"(a));
}
__device__ __forceinline__ void mma_bf16(float* d, const uint32_t* a,
                                         const uint32_t* b) {
    asm volatile(
        "mma.sync.aligned.m16n8k16.row.col.f32.bf16.bf16.f32 "
        "{%0,%1,%2,%3}, {%4,%5,%6,%7}, {%8,%9}, {%0,%1,%2,%3};"
        : "+f"(d[0]), "+f"(d[1]), "+f"(d[2]), "+f"(d[3])
        : "r"(a[0]), "r"(a[1]), "r"(a[2]), "r"(a[3]), "r"(b[0]), "r"(b[1]));
}
__device__ __forceinline__ unsigned pack_bf16(__nv_bfloat16 a, __nv_bfloat16 b) {
    return ((unsigned)__bfloat16_as_ushort(b) << 16) | (unsigned)__bfloat16_as_ushort(a);
}
__device__ __forceinline__ void cp16(uint32_t dst, const void* src) {
    asm volatile("cp.async.cg.shared.global [%0], [%1], 16;"
                 :: "r"(dst), "l"(src));
}
#define CP_COMMIT() asm volatile("cp.async.commit_group;" ::: "memory")
#define CP_WAIT0()  asm volatile("cp.async.wait_group 0;"  ::: "memory")

// ---------------------------------------------------------------------------
// generic fp32 -> bf16 hi/lo split
// ---------------------------------------------------------------------------
__global__ void split_kernel(const float* __restrict__ src,
                             __nv_bfloat16* __restrict__ h,
                             __nv_bfloat16* __restrict__ l)
{
    size_t i4 = (size_t)blockIdx.x * 256 + threadIdx.x;
    float4 v = *(const float4*)(src + i4 * 4);
    float f[4] = {v.x, v.y, v.z, v.w};
    __nv_bfloat16 hh[4], ll[4];
#pragma unroll
    for (int i = 0; i < 4; i++) {
        hh[i] = __float2bfloat16_rn(f[i]);
        ll[i] = __float2bfloat16_rn(f[i] - __bfloat162float(hh[i]));
    }
    *(uint2*)(h + i4 * 4) = make_uint2(pack_bf16(hh[0], hh[1]), pack_bf16(hh[2], hh[3]));
    *(uint2*)(l + i4 * 4) = make_uint2(pack_bf16(ll[0], ll[1]), pack_bf16(ll[2], ll[3]));
}

__global__ void init_bias_kernel(float* __restrict__ out,
                                 const float* __restrict__ bias)
{
    int idx = blockIdx.x * 256 + threadIdx.x;
    int cj = idx & 63;
    float4 bv = *(const float4*)&bias[cj * 4];
    *(float4*)&out[idx * 4] = bv;
}

// ---------------------------------------------------------------------------
// Projection via warp MMA (bf16 split, 3 terms)
// ---------------------------------------------------------------------------
template<int MT>
__global__ __launch_bounds__(256) void proj_mma_kernel(
    const __nv_bfloat16* __restrict__ Ah, const __nv_bfloat16* __restrict__ Al,
    const __nv_bfloat16* __restrict__ Wh, const __nv_bfloat16* __restrict__ Wl,
    const float* __restrict__ bias, int KDIM,
    float* __restrict__ outF, int atomicF,
    __nv_bfloat16* __restrict__ outH, __nv_bfloat16* __restrict__ outL)
{
    constexpr int NRW  = MT / 32;
    constexpr int NCW  = 8 / NRW;
    constexpr int WCOL = 256 / NCW;
    constexpr int NF   = WCOL / 8;
    constexpr int NP   = WCOL / 16;
    constexpr int AST  = 72, WST = 264;

    extern __shared__ char smbuf[];
    __nv_bfloat16* sAh = (__nv_bfloat16*)smbuf;
    __nv_bfloat16* sAl = sAh + MT * AST;
    __nv_bfloat16* sWh = sAl + MT * AST;
    __nv_bfloat16* sWl = sWh + 64 * WST;

    const int t = threadIdx.x, w = t >> 5, l = t & 31;
    const int wr = w / NCW, wc = w % NCW;
    const int aRow = l & 15, aCol = (l >> 4) * 8;
    const int row0 = blockIdx.x * MT;
    const int kd  = KDIM / gridDim.y;
    const int kb0 = blockIdx.y * kd;

    float acc[2][NF][4];
#pragma unroll
    for (int mf = 0; mf < 2; mf++)
#pragma unroll
        for (int nf = 0; nf < NF; nf++)
#pragma unroll
            for (int e = 0; e < 4; e++) acc[mf][nf][e] = 0.f;

    const uint32_t sa_h = smem_u32(sAh), sa_l = smem_u32(sAl);
    const uint32_t sw_h = smem_u32(sWh), sw_l = smem_u32(sWl);

    for (int kb = 0; kb < kd; kb += 64) {
        const int kg = kb0 + kb;
        __syncthreads();
        for (int idx = t; idx < MT * 8; idx += 256) {
            int r = idx >> 3, c = idx & 7;
            *(uint4*)(sAh + r * AST + c * 8) =
                *(const uint4*)(Ah + (size_t)(row0 + r) * KDIM + kg + c * 8);
            *(uint4*)(sAl + r * AST + c * 8) =
                *(const uint4*)(Al + (size_t)(row0 + r) * KDIM + kg + c * 8);
        }
        for (int idx = t; idx < 64 * 32; idx += 256) {
            int r = idx >> 5, c = idx & 31;
            *(uint4*)(sWh + r * WST + c * 8) =
                *(const uint4*)(Wh + (size_t)(kg + r) * 256 + c * 8);
            *(uint4*)(sWl + r * WST + c * 8) =
                *(const uint4*)(Wl + (size_t)(kg + r) * 256 + c * 8);
        }
        __syncthreads();
#pragma unroll
        for (int ks = 0; ks < 4; ks++) {
            uint32_t ah[2][4], al[2][4];
#pragma unroll
            for (int mf = 0; mf < 2; mf++) {
                uint32_t off = (uint32_t)((wr * 32 + mf * 16 + aRow) * AST +
                                          ks * 16 + aCol) * 2;
                ldsm4(ah[mf], sa_h + off);
                ldsm4(al[mf], sa_l + off);
            }
#pragma unroll
            for (int p = 0; p < NP; p++) {
                uint32_t bh[4], bl[4];
                uint32_t off = (uint32_t)((ks * 16 + aRow) * WST +
                                          wc * WCOL + p * 16 + aCol) * 2;
                ldsm4t(bh, sw_h + off);
                ldsm4t(bl, sw_l + off);
#pragma unroll
                for (int mf = 0; mf < 2; mf++)
#pragma unroll
                    for (int sub = 0; sub < 2; sub++) {
                        mma_bf16(acc[mf][p * 2 + sub], ah[mf], &bh[sub * 2]);
                        mma_bf16(acc[mf][p * 2 + sub], ah[mf], &bl[sub * 2]);
                        mma_bf16(acc[mf][p * 2 + sub], al[mf], &bh[sub * 2]);
                    }
            }
        }
    }

#pragma unroll
    for (int mf = 0; mf < 2; mf++)
#pragma unroll
    for (int nf = 0; nf < NF; nf++)
#pragma unroll
    for (int pr = 0; pr < 2; pr++) {
        int r = row0 + wr * 32 + mf * 16 + (l >> 2) + pr * 8;
        int c = wc * WCOL + nf * 8 + (l & 3) * 2;
        float v0 = acc[mf][nf][pr * 2 + 0];
        float v1 = acc[mf][nf][pr * 2 + 1];
        if (atomicF) {
            atomicAdd(outF + (size_t)r * 256 + c,     v0);
            atomicAdd(outF + (size_t)r * 256 + c + 1, v1);
        } else {
            v0 += bias[c]; v1 += bias[c + 1];
            if (outF) *(float2*)(outF + (size_t)r * 256 + c) = make_float2(v0, v1);
            if (outH) {
                __nv_bfloat16 h0 = __float2bfloat16_rn(v0);
                __nv_bfloat16 l0 = __float2bfloat16_rn(v0 - __bfloat162float(h0));
                __nv_bfloat16 h1 = __float2bfloat16_rn(v1);
                __nv_bfloat16 l1 = __float2bfloat16_rn(v1 - __bfloat162float(h1));
                *(uint32_t*)(outH + (size_t)r * 256 + c) = pack_bf16(h0, h1);
                *(uint32_t*)(outL + (size_t)r * 256 + c) = pack_bf16(l0, l1);
            }
        }
    }
}

// ---------------------------------------------------------------------------
// Gram att2 via warp MMA (NT)
// ---------------------------------------------------------------------------
__global__ __launch_bounds__(256) void gram_mma_kernel(
    const __nv_bfloat16* __restrict__ Xh, const __nv_bfloat16* __restrict__ Xl,
    float* __restrict__ out, int N)
{
    constexpr int XST = 72;
    extern __shared__ char smbuf[];
    __nv_bfloat16* sIh = (__nv_bfloat16*)smbuf;
    __nv_bfloat16* sIl = sIh + 128 * XST;
    __nv_bfloat16* sJh = sIl + 128 * XST;
    __nv_bfloat16* sJl = sJh + 128 * XST;

    const int b = blockIdx.z;
    const int i0 = blockIdx.x * 128, j0 = blockIdx.y * 128;
    const int t = threadIdx.x, w = t >> 5, l = t & 31;
    const int wr = w >> 1, wc = w & 1;
    const int aRow = l & 15, aCol = (l >> 4) * 8;
    const int bRow = (l >> 4) * 8 + (l & 7), bCol = ((l >> 3) & 1) * 8;
    const __nv_bfloat16* Xbh = Xh + (size_t)b * N * CCH;
    const __nv_bfloat16* Xbl = Xl + (size_t)b * N * CCH;

    float acc[2][8][4];
#pragma unroll
    for (int mf = 0; mf < 2; mf++)
#pragma unroll
        for (int nf = 0; nf < 8; nf++)
#pragma unroll
            for (int e = 0; e < 4; e++) acc[mf][nf][e] = 0.f;

    const uint32_t si_h = smem_u32(sIh), si_l = smem_u32(sIl);
    const uint32_t sj_h = smem_u32(sJh), sj_l = smem_u32(sJl);

    for (int kb = 0; kb < CCH; kb += 64) {
        __syncthreads();
        for (int idx = t; idx < 128 * 8; idx += 256) {
            int r = idx >> 3, c = idx & 7;
            *(uint4*)(sIh + r * XST + c * 8) =
                *(const uint4*)(Xbh + (size_t)(i0 + r) * CCH + kb + c * 8);
            *(uint4*)(sIl + r * XST + c * 8) =
                *(const uint4*)(Xbl + (size_t)(i0 + r) * CCH + kb + c * 8);
            *(uint4*)(sJh + r * XST + c * 8) =
                *(const uint4*)(Xbh + (size_t)(j0 + r) * CCH + kb + c * 8);
            *(uint4*)(sJl + r * XST + c * 8) =
                *(const uint4*)(Xbl + (size_t)(j0 + r) * CCH + kb + c * 8);
        }
        __syncthreads();
#pragma unroll
        for (int ks = 0; ks < 4; ks++) {
            uint32_t ah[2][4], al[2][4];
#pragma unroll
            for (int mf = 0; mf < 2; mf++) {
                uint32_t off = (uint32_t)((wr * 32 + mf * 16 + aRow) * XST +
                                          ks * 16 + aCol) * 2;
                ldsm4(ah[mf], si_h + off);
                ldsm4(al[mf], si_l + off);
            }
#pragma unroll
            for (int bt = 0; bt < 4; bt++) {
                uint32_t bh[4], bl[4];
                uint32_t off = (uint32_t)((wc * 64 + bt * 16 + bRow) * XST +
                                          ks * 16 + bCol) * 2;
                ldsm4(bh, sj_h + off);
                ldsm4(bl, sj_l + off);
#pragma unroll
                for (int mf = 0; mf < 2; mf++)
#pragma unroll
                    for (int sub = 0; sub < 2; sub++) {
                        mma_bf16(acc[mf][bt * 2 + sub], ah[mf], &bh[sub * 2]);
                        mma_bf16(acc[mf][bt * 2 + sub], ah[mf], &bl[sub * 2]);
                        mma_bf16(acc[mf][bt * 2 + sub], al[mf], &bh[sub * 2]);
                    }
            }
        }
    }

#pragma unroll
    for (int mf = 0; mf < 2; mf++)
#pragma unroll
    for (int nf = 0; nf < 8; nf++)
#pragma unroll
    for (int pr = 0; pr < 2; pr++) {
        int i = i0 + wr * 32 + mf * 16 + (l >> 2) + pr * 8;
        int j = j0 + wc * 64 + nf * 8 + (l & 3) * 2;
        *(float2*)(out + (size_t)b * N * N + (size_t)i * N + j) =
            make_float2(acc[mf][nf][pr * 2 + 0], acc[mf][nf][pr * 2 + 1]);
    }
}

// ---------------------------------------------------------------------------
// Gram 64x64 (att3, fp32)
// ---------------------------------------------------------------------------
__global__ __launch_bounds__(256) void attnt_kernel(
    const float* __restrict__ X, float* __restrict__ out, int N)
{
    __shared__ float Ai[32][65];
    __shared__ float Bj[32][65];
    const int b  = blockIdx.z;
    const int i0 = blockIdx.x * 64, j0 = blockIdx.y * 64;
    const int t  = threadIdx.x;
    const int ty = t >> 4, tx = t & 15;
    const int r0 = ty * 4, c0 = tx * 4;
    const float* Xb = X + (size_t)b * N * CCH;

    float acc[4][4] = {};
    for (int k0 = 0; k0 < CCH; k0 += 32) {
#pragma unroll
        for (int i = 0; i < 8; i++) {
            int lin = t + 256 * i;
            int r = lin >> 5, k = lin & 31;
            Ai[k][r] = Xb[(size_t)(i0 + r) * CCH + k0 + k];
            Bj[k][r] = Xb[(size_t)(j0 + r) * CCH + k0 + k];
        }
        __syncthreads();
#pragma unroll
        for (int k = 0; k < 32; k++) {
            float a[4], bb[4];
#pragma unroll
            for (int i = 0; i < 4; i++) a[i]  = Ai[k][r0 + i];
#pragma unroll
            for (int j = 0; j < 4; j++) bb[j] = Bj[k][c0 + j];
#pragma unroll
            for (int i = 0; i < 4; i++)
#pragma unroll
                for (int j = 0; j < 4; j++)
                    acc[i][j] += a[i] * bb[j];
        }
        __syncthreads();
    }
#pragma unroll
    for (int i = 0; i < 4; i++) {
        float4 o = make_float4(acc[i][0], acc[i][1], acc[i][2], acc[i][3]);
        *(float4*)&out[(size_t)b * N * N + (size_t)(i0 + r0 + i) * N + j0 + c0] = o;
    }
}

// ---------------------------------------------------------------------------
// Fused sigmoid-attention: 32-row m-tiles, full 256 ch, cp.async double-buffer
// 8 warps: wn = w&3 (16 n-rows), wc = w>>2 (m-col half / ch half)
// ---------------------------------------------------------------------------
#define KST  264
#define SSTR 40

__global__ __launch_bounds__(256, 1) void fused_mma_kernel(
    const __nv_bfloat16* __restrict__ xh, const __nv_bfloat16* __restrict__ xl,
    const float* __restrict__ p1,
    const float* __restrict__ att2, const float* __restrict__ att3,
    const float* __restrict__ pa1, const float* __restrict__ pa2,
    const float* __restrict__ pa3, float* __restrict__ out)
{
    extern __shared__ char smbuf[];
    __nv_bfloat16* Qh = (__nv_bfloat16*)smbuf;          // 64 x 264
    __nv_bfloat16* Ql = Qh + 64 * KST;
    __nv_bfloat16* Kb = Ql + 64 * KST;                  // 4 x (32 x 264): b0h,b0l,b1h,b1l
    __nv_bfloat16* Sh = Kb + 4 * 32 * KST;              // 64 x 40
    __nv_bfloat16* Sl = Sh + 64 * SSTR;
    float* A2s = (float*)(Sl + 64 * SSTR);              // 17 x 257
    float* A3s = A2s + 17 * 257;                        // 5 x 65

    const int b  = blockIdx.y;
    const int n0 = blockIdx.x * 64;
    const int t  = threadIdx.x, w = t >> 5, l = t & 31;
    const int wn = w & 3, wc = w >> 2;
    const int aRow = l & 15, aCol = (l >> 4) * 8;
    const int bRow = (l >> 4) * 8 + (l & 7);
    const int bCol = ((l >> 3) & 1) * 8;

    const __nv_bfloat16* Xh = xh + (size_t)b * N1D * CCH;
    const __nv_bfloat16* Xl = xl + (size_t)b * N1D * CCH;
    const float sa1 = *pa1, sa2 = *pa2, sa3 = *pa3;
    const int r2lo = n0 >> 2, r3lo = n0 >> 4;

    // ---- stage Q (64 x 256) ----
#pragma unroll
    for (int i = 0; i < 8; i++) {
        int idx = t + 256 * i;               // 2048 = 64 rows x 32 chunks
        int r = idx >> 5, c = idx & 31;
        *(uint4*)(Qh + r * KST + c * 8) =
            *(const uint4*)(Xh + (size_t)(n0 + r) * CCH + c * 8);
        *(uint4*)(Ql + r * KST + c * 8) =
            *(const uint4*)(Xl + (size_t)(n0 + r) * CCH + c * 8);
    }
    // ---- gating windows ----
    for (int i = t; i < 17 * 256; i += 256) {
        int rr = i >> 8, cc = i & 255;
        A2s[rr * 257 + cc] = att2[((size_t)b * 256 + min(r2lo + rr, 255)) * 256 + cc];
    }
    for (int i = t; i < 5 * 64; i += 256) {
        int rr = i >> 6, cc = i & 63;
        A3s[rr * 65 + cc] = att3[((size_t)b * 64 + min(r3lo + rr, 63)) * 64 + cc];
    }

    const uint32_t qh0 = smem_u32(Qh), ql0 = smem_u32(Ql);
    const uint32_t kb0 = smem_u32(Kb);
    const uint32_t sh0 = smem_u32(Sh), sl0 = smem_u32(Sl);
    const uint32_t TB  = 32 * KST * 2;   // bytes per K tensor buffer

    // gating constants for this thread's 2 output rows
    const float *R0p[2], *R1p[2], *T0p[2], *T1p[2];
    float fnv[2], fn3v[2];
#pragma unroll
    for (int pr = 0; pr < 2; pr++) {
        int n = n0 + wn * 16 + (l >> 2) + pr * 8;
        int rn = n >> 2;
        fnv[pr] = (float)(n & 3) * 0.25f;
        R0p[pr] = A2s + (rn - r2lo) * 257;
        R1p[pr] = A2s + (min(rn + 1, 255) - r2lo) * 257;
        int rn3 = n >> 4;
        fn3v[pr] = (float)(n & 15) * 0.0625f;
        T0p[pr] = A3s + (rn3 - r3lo) * 65;
        T1p[pr] = A3s + (min(rn3 + 1, 63) - r3lo) * 65;
    }

    float O[16][4];
#pragma unroll
    for (int f = 0; f < 16; f++)
#pragma unroll
        for (int e = 0; e < 4; e++) O[f][e] = 0.f;

    // ---- prefetch m-tile 0 ----
#pragma unroll
    for (int s = 0; s < 4; s++) {
        int idx = t + 256 * s;               // 1024 = 32 rows x 32 chunks
        int r = idx >> 5, c = idx & 31;
        uint32_t doff = (uint32_t)(r * KST + c * 8) * 2;
        cp16(kb0 + doff,      Xh + (size_t)r * CCH + c * 8);
        cp16(kb0 + TB + doff, Xl + (size_t)r * CCH + c * 8);
    }
    CP_COMMIT();

    for (int mt = 0; mt < 32; mt++) {
        const int m0 = mt * 32;
        CP_WAIT0();
        __syncthreads();                     // tile mt visible; GEMM2(mt-1) done
        const uint32_t kh = kb0 + (uint32_t)(mt & 1) * (2 * TB);
        const uint32_t kl = kh + TB;

        // ---- GEMM1: S(64x32) = Q . K^T ----
        float Sa[2][4];
#pragma unroll
        for (int nf = 0; nf < 2; nf++)
#pragma unroll
            for (int e = 0; e < 4; e++) Sa[nf][e] = 0.f;

#pragma unroll
        for (int kc = 0; kc < 16; kc++) {
            uint32_t ah[4], al[4];
            uint32_t offA = (uint32_t)((wn * 16 + aRow) * KST + kc * 16 + aCol) * 2;
            ldsm4(ah, qh0 + offA);
            ldsm4(al, ql0 + offA);
            uint32_t rh[4], rl[4];
            uint32_t offB = (uint32_t)((wc * 16 + bRow) * KST + kc * 16 + bCol) * 2;
            ldsm4(rh, kh + offB);
            ldsm4(rl, kl + offB);
            mma_bf16(Sa[0], ah, &rh[0]); mma_bf16(Sa[0], ah, &rl[0]);
            mma_bf16(Sa[0], al, &rh[0]);
            mma_bf16(Sa[1], ah, &rh[2]); mma_bf16(Sa[1], ah, &rl[2]);
            mma_bf16(Sa[1], al, &rh[2]);
        }

        // ---- epilogue: gating + sigmoid -> Sh/Sl ----
#pragma unroll
        for (int nf = 0; nf < 2; nf++)
#pragma unroll
        for (int pr = 0; pr < 2; pr++) {
            const int row_l = wn * 16 + (l >> 2) + pr * 8;
            const int col_l = wc * 16 + nf * 8 + (l & 3) * 2;
            const float fn = fnv[pr], fn3 = fn3v[pr];
            const float *R0 = R0p[pr], *R1 = R1p[pr];
            const float *T0 = T0p[pr], *T1 = T1p[pr];
            __nv_bfloat16 hh[2], hl[2];
#pragma unroll
            for (int e = 0; e < 2; e++) {
                int m = m0 + col_l + e;
                float Sv = Sa[nf][pr * 2 + e];
                int cm = m >> 2;
                float fm = (float)(m & 3) * 0.25f;
                int cm1 = min(cm + 1, 255);
                float v2 = (1.f - fn) * ((1.f - fm) * R0[cm] + fm * R0[cm1]) +
                           fn         * ((1.f - fm) * R1[cm] + fm * R1[cm1]);
                int cm3 = m >> 4;
                float fm3 = (float)(m & 15) * 0.0625f;
                int cm31 = min(cm3 + 1, 63);
                float v3 = (1.f - fn3) * ((1.f - fm3) * T0[cm3] + fm3 * T0[cm31]) +
                           fn3         * ((1.f - fm3) * T1[cm3] + fm3 * T1[cm31]);
                float val = sa1 * Sv + sa2 * v2 + sa3 * v3;
                float sg = 1.0f / (1.0f + __expf(-val));
                hh[e] = __float2bfloat16_rn(sg);
                hl[e] = __float2bfloat16_rn(sg - __bfloat162float(hh[e]));
            }
            *(uint32_t*)&Sh[row_l * SSTR + col_l] = pack_bf16(hh[0], hh[1]);
            *(uint32_t*)&Sl[row_l * SSTR + col_l] = pack_bf16(hl[0], hl[1]);
        }
        __syncthreads();                     // S visible

        // ---- prefetch next tile into the other buffer ----
        if (mt + 1 < 32) {
            const __nv_bfloat16* nH = Xh + (size_t)(m0 + 32) * CCH;
            const __nv_bfloat16* nL = Xl + (size_t)(m0 + 32) * CCH;
            uint32_t kdst = kb0 + (uint32_t)((mt + 1) & 1) * (2 * TB);
#pragma unroll
            for (int s = 0; s < 4; s++) {
                int idx = t + 256 * s;
                int r = idx >> 5, c = idx & 31;
                uint32_t doff = (uint32_t)(r * KST + c * 8) * 2;
                cp16(kdst + doff,      nH + (size_t)r * CCH + c * 8);
                cp16(kdst + TB + doff, nL + (size_t)r * CCH + c * 8);
            }
            CP_COMMIT();
        }

        // ---- GEMM2: O(64x256) += S . K ----
#pragma unroll
        for (int kc = 0; kc < 2; kc++) {
            uint32_t sAh[4], sAl[4];
            uint32_t offA = (uint32_t)((wn * 16 + aRow) * SSTR + kc * 16 + aCol) * 2;
            ldsm4(sAh, sh0 + offA);
            ldsm4(sAl, sl0 + offA);
#pragma unroll
            for (int p = 0; p < 8; p++) {
                uint32_t rh[4], rl[4];
                uint32_t offB = (uint32_t)((kc * 16 + aRow) * KST +
                                           wc * 128 + p * 16 + aCol) * 2;
                ldsm4t(rh, kh + offB);
                ldsm4t(rl, kl + offB);
                mma_bf16(O[p * 2],     sAh, &rh[0]); mma_bf16(O[p * 2],     sAh, &rl[0]);
                mma_bf16(O[p * 2],     sAl, &rh[0]);
                mma_bf16(O[p * 2 + 1], sAh, &rh[2]); mma_bf16(O[p * 2 + 1], sAh, &rl[2]);
                mma_bf16(O[p * 2 + 1], sAl, &rh[2]);
            }
        }
    }

    // ---- final: out = O + p1 ----
#pragma unroll
    for (int f = 0; f < 16; f++)
#pragma unroll
    for (int pr = 0; pr < 2; pr++) {
        const int n  = n0 + wn * 16 + (l >> 2) + pr * 8;
        const int ch = wc * 128 + f * 8 + (l & 3) * 2;
        const size_t o = ((size_t)(b * N1D + n)) * CCH + ch;
        float2 pv = *(const float2*)(p1 + o);
        *(float2*)(out + o) = make_float2(O[f][pr * 2 + 0] + pv.x,
                                          O[f][pr * 2 + 1] + pv.y);
    }
}

// ---------------------------------------------------------------------------
extern "C" void kernel_launch(void* const* d_in, const int* in_sizes, int n_in,
                              void* d_out, int out_size)
{
    const float* f1 = (const float*)d_in[0];
    const float* f2 = (const float*)d_in[1];
    const float* f3 = (const float*)d_in[2];
    const float* w1 = (const float*)d_in[3];
    const float* b1 = (const float*)d_in[4];
    const float* w2 = (const float*)d_in[5];
    const float* b2 = (const float*)d_in[6];
    const float* w3 = (const float*)d_in[7];
    const float* b3 = (const float*)d_in[8];
    const float* a1 = (const float*)d_in[9];
    const float* a2 = (const float*)d_in[10];
    const float* a3 = (const float*)d_in[11];
    float* out = (float*)d_out;

    float *p1, *x3, *att2, *att3;
    __nv_bfloat16 *x1h, *x1l, *x2h, *x2l;
    __nv_bfloat16 *f1h, *f1l, *f2h, *f2l, *f3h, *f3l;
    __nv_bfloat16 *w1h, *w1l, *w2h, *w2l, *w3h, *w3l;
    cudaGetSymbolAddress((void**)&p1,   g_p1);
    cudaGetSymbolAddress((void**)&x3,   g_x3);
    cudaGetSymbolAddress((void**)&att2, g_att2);
    cudaGetSymbolAddress((void**)&att3, g_att3);
    cudaGetSymbolAddress((void**)&x1h,  g_x1h);
    cudaGetSymbolAddress((void**)&x1l,  g_x1l);
    cudaGetSymbolAddress((void**)&x2h,  g_x2h);
    cudaGetSymbolAddress((void**)&x2l,  g_x2l);
    cudaGetSymbolAddress((void**)&f1h,  g_f1h);
    cudaGetSymbolAddress((void**)&f1l,  g_f1l);
    cudaGetSymbolAddress((void**)&f2h,  g_f2h);
    cudaGetSymbolAddress((void**)&f2l,  g_f2l);
    cudaGetSymbolAddress((void**)&f3h,  g_f3h);
    cudaGetSymbolAddress((void**)&f3l,  g_f3l);
    cudaGetSymbolAddress((void**)&w1h,  g_w1h);
    cudaGetSymbolAddress((void**)&w1l,  g_w1l);
    cudaGetSymbolAddress((void**)&w2h,  g_w2h);
    cudaGetSymbolAddress((void**)&w2l,  g_w2l);
    cudaGetSymbolAddress((void**)&w3h,  g_w3h);
    cudaGetSymbolAddress((void**)&w3l,  g_w3l);

    split_kernel<<<(BATCH * N1D * CCH) / 1024, 256>>>(f1, f1h, f1l);
    split_kernel<<<(BATCH * 256 * 512) / 1024, 256>>>(f2, f2h, f2l);
    split_kernel<<<(BATCH * 64 * 1024) / 1024, 256>>>(f3, f3h, f3l);
    split_kernel<<<(256 * 256)   / 1024, 256>>>(w1, w1h, w1l);
    split_kernel<<<(512 * 256)   / 1024, 256>>>(w2, w2h, w2l);
    split_kernel<<<(1024 * 256)  / 1024, 256>>>(w3, w3h, w3l);

    init_bias_kernel<<<(BATCH * 64 * CCH) / 1024, 256>>>(x3, b3);

    const int smemP128 = (128 * 72 * 2 + 64 * 264 * 2) * 2;
    const int smemP64  = (64  * 72 * 2 + 64 * 264 * 2) * 2;
    cudaFuncSetAttribute(proj_mma_kernel<128>,
                         cudaFuncAttributeMaxDynamicSharedMemorySize, smemP128);
    cudaFuncSetAttribute(proj_mma_kernel<64>,
                         cudaFuncAttributeMaxDynamicSharedMemorySize, smemP64);

    proj_mma_kernel<128><<<dim3(128, 1), 256, smemP128>>>(
        f1h, f1l, w1h, w1l, b1, 256, p1, 0, x1h, x1l);
    proj_mma_kernel<64><<<dim3(64, 1), 256, smemP64>>>(
        f2h, f2l, w2h, w2l, b2, 512, nullptr, 0, x2h, x2l);
    proj_mma_kernel<64><<<dim3(16, 4), 256, smemP64>>>(
        f3h, f3l, w3h, w3l, b3, 1024, x3, 1, nullptr, nullptr);

    const int smemG = 4 * 128 * 72 * 2;
    cudaFuncSetAttribute(gram_mma_kernel,
                         cudaFuncAttributeMaxDynamicSharedMemorySize, smemG);
    gram_mma_kernel<<<dim3(2, 2, BATCH), 256, smemG>>>(x2h, x2l, att2, 256);

    attnt_kernel<<<dim3(1, 1, BATCH), 256>>>(x3, att3, 64);

    const int smemF =
        (64 * KST + 4 * 32 * KST + 2 * 64 * SSTR) * 2 * 2   // bf16 tiles (Q + Kx4 + S)
        / 2                                                  // (elements*2B)
        + (17 * 257 + 5 * 65) * 4;
    // explicit: (64*264*2 + 4*32*264 + 2*64*40) elements * 2 bytes + gating
    const int smemF2 = (64 * KST * 2 + 4 * 32 * KST + 2 * 64 * SSTR) * 2
                       + (17 * 257 + 5 * 65) * 4;
    (void)smemF;
    cudaFuncSetAttribute(fused_mma_kernel,
                         cudaFuncAttributeMaxDynamicSharedMemorySize, smemF2);
    fused_mma_kernel<<<dim3(16, BATCH), 256, smemF2>>>(
        x1h, x1l, p1, att2, att3, a1, a2, a3, out);
}

// round 9
// speedup vs baseline: 1.0743x; 1.0743x over previous
#include <cuda_runtime.h>
#include <cuda_bf16.h>
#include <math.h>
#include <stdint.h>

#define BATCH 16
#define N1D 1024
#define CCH 256

// ---------------- device scratch ----------------
__device__ float g_p1[BATCH * N1D * CCH];
__device__ float g_x3[BATCH * 64 * CCH];
__device__ float g_att2[BATCH * 256 * 256];
__device__ float g_att3[BATCH * 64 * 64];
__device__ __nv_bfloat16 g_x1h[BATCH * N1D * CCH];
__device__ __nv_bfloat16 g_x1l[BATCH * N1D * CCH];
__device__ __nv_bfloat16 g_x2h[BATCH * 256 * CCH];
__device__ __nv_bfloat16 g_x2l[BATCH * 256 * CCH];
__device__ __nv_bfloat16 g_f1h[BATCH * N1D * CCH];
__device__ __nv_bfloat16 g_f1l[BATCH * N1D * CCH];
__device__ __nv_bfloat16 g_f2h[BATCH * 256 * 512];
__device__ __nv_bfloat16 g_f2l[BATCH * 256 * 512];
__device__ __nv_bfloat16 g_f3h[BATCH * 64 * 1024];
__device__ __nv_bfloat16 g_f3l[BATCH * 64 * 1024];
__device__ __nv_bfloat16 g_w1h[256 * 256],  g_w1l[256 * 256];
__device__ __nv_bfloat16 g_w2h[512 * 256],  g_w2l[512 * 256];
__device__ __nv_bfloat16 g_w3h[1024 * 256], g_w3l[1024 * 256];

// ---------------- warp-MMA helpers ----------------
__device__ __forceinline__ uint32_t smem_u32(const void* p) {
    uint32_t a;
    asm("{ .reg .u64 t; cvta.to.shared.u64 t, %1; cvt.u32.u64 %0, t; }"
        : "=r"(a) : "l"(p));
    return a;
}
__device__ __forceinline__ void ldsm4(uint32_t* r, uint32_t a) {
    asm volatile("ldmatrix.sync.aligned.m8n8.x4.shared.b16 {%0,%1,%2,%3}, [%4];"
        : "=r"(r[0]), "=r"(r[1]), "=r"(r[2]), "=r"(r[3]) : "r"(a));
}
__device__ __forceinline__ void ldsm4t(uint32_t* r, uint32_t a) {
    asm volatile("ldmatrix.sync.aligned.m8n8.x4.trans.shared.b16 {%0,%1,%2,%3}, [%4];"
        : "=r"(r[0]), "=r"(r[1]), "=r"(r[2]), "=r"(r[3]) : "r"(a));
}
__device__ __forceinline__ void mma_bf16(float* d, const uint32_t* a,
                                         const uint32_t* b) {
    asm volatile(
        "mma.sync.aligned.m16n8k16.row.col.f32.bf16.bf16.f32 "
        "{%0,%1,%2,%3}, {%4,%5,%6,%7}, {%8,%9}, {%0,%1,%2,%3};"
        : "+f"(d[0]), "+f"(d[1]), "+f"(d[2]), "+f"(d[3])
        : "r"(a[0]), "r"(a[1]), "r"(a[2]), "r"(a[3]), "r"(b[0]), "r"(b[1]));
}
__device__ __forceinline__ unsigned pack_bf16(__nv_bfloat16 a, __nv_bfloat16 b) {
    return ((unsigned)__bfloat16_as_ushort(b) << 16) | (unsigned)__bfloat16_as_ushort(a);
}

// ---------------------------------------------------------------------------
// generic fp32 -> bf16 hi/lo split
// ---------------------------------------------------------------------------
__global__ void split_kernel(const float* __restrict__ src,
                             __nv_bfloat16* __restrict__ h,
                             __nv_bfloat16* __restrict__ l)
{
    size_t i4 = (size_t)blockIdx.x * 256 + threadIdx.x;
    float4 v = *(const float4*)(src + i4 * 4);
    float f[4] = {v.x, v.y, v.z, v.w};
    __nv_bfloat16 hh[4], ll[4];
#pragma unroll
    for (int i = 0; i < 4; i++) {
        hh[i] = __float2bfloat16_rn(f[i]);
        ll[i] = __float2bfloat16_rn(f[i] - __bfloat162float(hh[i]));
    }
    *(uint2*)(h + i4 * 4) = make_uint2(pack_bf16(hh[0], hh[1]), pack_bf16(hh[2], hh[3]));
    *(uint2*)(l + i4 * 4) = make_uint2(pack_bf16(ll[0], ll[1]), pack_bf16(ll[2], ll[3]));
}

__global__ void init_bias_kernel(float* __restrict__ out,
                                 const float* __restrict__ bias)
{
    int idx = blockIdx.x * 256 + threadIdx.x;
    int cj = idx & 63;
    float4 bv = *(const float4*)&bias[cj * 4];
    *(float4*)&out[idx * 4] = bv;
}

// ---------------------------------------------------------------------------
// Projection via warp MMA (bf16 split, 3 terms)
// ---------------------------------------------------------------------------
template<int MT>
__global__ __launch_bounds__(256) void proj_mma_kernel(
    const __nv_bfloat16* __restrict__ Ah, const __nv_bfloat16* __restrict__ Al,
    const __nv_bfloat16* __restrict__ Wh, const __nv_bfloat16* __restrict__ Wl,
    const float* __restrict__ bias, int KDIM,
    float* __restrict__ outF, int atomicF,
    __nv_bfloat16* __restrict__ outH, __nv_bfloat16* __restrict__ outL)
{
    constexpr int NRW  = MT / 32;
    constexpr int NCW  = 8 / NRW;
    constexpr int WCOL = 256 / NCW;
    constexpr int NF   = WCOL / 8;
    constexpr int NP   = WCOL / 16;
    constexpr int AST  = 72, WST = 264;

    extern __shared__ char smbuf[];
    __nv_bfloat16* sAh = (__nv_bfloat16*)smbuf;
    __nv_bfloat16* sAl = sAh + MT * AST;
    __nv_bfloat16* sWh = sAl + MT * AST;
    __nv_bfloat16* sWl = sWh + 64 * WST;

    const int t = threadIdx.x, w = t >> 5, l = t & 31;
    const int wr = w / NCW, wc = w % NCW;
    const int aRow = l & 15, aCol = (l >> 4) * 8;
    const int row0 = blockIdx.x * MT;
    const int kd  = KDIM / gridDim.y;
    const int kb0 = blockIdx.y * kd;

    float acc[2][NF][4];
#pragma unroll
    for (int mf = 0; mf < 2; mf++)
#pragma unroll
        for (int nf = 0; nf < NF; nf++)
#pragma unroll
            for (int e = 0; e < 4; e++) acc[mf][nf][e] = 0.f;

    const uint32_t sa_h = smem_u32(sAh), sa_l = smem_u32(sAl);
    const uint32_t sw_h = smem_u32(sWh), sw_l = smem_u32(sWl);

    for (int kb = 0; kb < kd; kb += 64) {
        const int kg = kb0 + kb;
        __syncthreads();
        for (int idx = t; idx < MT * 8; idx += 256) {
            int r = idx >> 3, c = idx & 7;
            *(uint4*)(sAh + r * AST + c * 8) =
                *(const uint4*)(Ah + (size_t)(row0 + r) * KDIM + kg + c * 8);
            *(uint4*)(sAl + r * AST + c * 8) =
                *(const uint4*)(Al + (size_t)(row0 + r) * KDIM + kg + c * 8);
        }
        for (int idx = t; idx < 64 * 32; idx += 256) {
            int r = idx >> 5, c = idx & 31;
            *(uint4*)(sWh + r * WST + c * 8) =
                *(const uint4*)(Wh + (size_t)(kg + r) * 256 + c * 8);
            *(uint4*)(sWl + r * WST + c * 8) =
                *(const uint4*)(Wl + (size_t)(kg + r) * 256 + c * 8);
        }
        __syncthreads();
#pragma unroll
        for (int ks = 0; ks < 4; ks++) {
            uint32_t ah[2][4], al[2][4];
#pragma unroll
            for (int mf = 0; mf < 2; mf++) {
                uint32_t off = (uint32_t)((wr * 32 + mf * 16 + aRow) * AST +
                                          ks * 16 + aCol) * 2;
                ldsm4(ah[mf], sa_h + off);
                ldsm4(al[mf], sa_l + off);
            }
#pragma unroll
            for (int p = 0; p < NP; p++) {
                uint32_t bh[4], bl[4];
                uint32_t off = (uint32_t)((ks * 16 + aRow) * WST +
                                          wc * WCOL + p * 16 + aCol) * 2;
                ldsm4t(bh, sw_h + off);
                ldsm4t(bl, sw_l + off);
#pragma unroll
                for (int mf = 0; mf < 2; mf++)
#pragma unroll
                    for (int sub = 0; sub < 2; sub++) {
                        mma_bf16(acc[mf][p * 2 + sub], ah[mf], &bh[sub * 2]);
                        mma_bf16(acc[mf][p * 2 + sub], ah[mf], &bl[sub * 2]);
                        mma_bf16(acc[mf][p * 2 + sub], al[mf], &bh[sub * 2]);
                    }
            }
        }
    }

#pragma unroll
    for (int mf = 0; mf < 2; mf++)
#pragma unroll
    for (int nf = 0; nf < NF; nf++)
#pragma unroll
    for (int pr = 0; pr < 2; pr++) {
        int r = row0 + wr * 32 + mf * 16 + (l >> 2) + pr * 8;
        int c = wc * WCOL + nf * 8 + (l & 3) * 2;
        float v0 = acc[mf][nf][pr * 2 + 0];
        float v1 = acc[mf][nf][pr * 2 + 1];
        if (atomicF) {
            atomicAdd(outF + (size_t)r * 256 + c,     v0);
            atomicAdd(outF + (size_t)r * 256 + c + 1, v1);
        } else {
            v0 += bias[c]; v1 += bias[c + 1];
            if (outF) *(float2*)(outF + (size_t)r * 256 + c) = make_float2(v0, v1);
            if (outH) {
                __nv_bfloat16 h0 = __float2bfloat16_rn(v0);
                __nv_bfloat16 l0 = __float2bfloat16_rn(v0 - __bfloat162float(h0));
                __nv_bfloat16 h1 = __float2bfloat16_rn(v1);
                __nv_bfloat16 l1 = __float2bfloat16_rn(v1 - __bfloat162float(h1));
                *(uint32_t*)(outH + (size_t)r * 256 + c) = pack_bf16(h0, h1);
                *(uint32_t*)(outL + (size_t)r * 256 + c) = pack_bf16(l0, l1);
            }
        }
    }
}

// ---------------------------------------------------------------------------
// Gram att2 via warp MMA (NT)
// ---------------------------------------------------------------------------
__global__ __launch_bounds__(256) void gram_mma_kernel(
    const __nv_bfloat16* __restrict__ Xh, const __nv_bfloat16* __restrict__ Xl,
    float* __restrict__ out, int N)
{
    constexpr int XST = 72;
    extern __shared__ char smbuf[];
    __nv_bfloat16* sIh = (__nv_bfloat16*)smbuf;
    __nv_bfloat16* sIl = sIh + 128 * XST;
    __nv_bfloat16* sJh = sIl + 128 * XST;
    __nv_bfloat16* sJl = sJh + 128 * XST;

    const int b = blockIdx.z;
    const int i0 = blockIdx.x * 128, j0 = blockIdx.y * 128;
    const int t = threadIdx.x, w = t >> 5, l = t & 31;
    const int wr = w >> 1, wc = w & 1;
    const int aRow = l & 15, aCol = (l >> 4) * 8;
    const int bRow = (l >> 4) * 8 + (l & 7), bCol = ((l >> 3) & 1) * 8;
    const __nv_bfloat16* Xbh = Xh + (size_t)b * N * CCH;
    const __nv_bfloat16* Xbl = Xl + (size_t)b * N * CCH;

    float acc[2][8][4];
#pragma unroll
    for (int mf = 0; mf < 2; mf++)
#pragma unroll
        for (int nf = 0; nf < 8; nf++)
#pragma unroll
            for (int e = 0; e < 4; e++) acc[mf][nf][e] = 0.f;

    const uint32_t si_h = smem_u32(sIh), si_l = smem_u32(sIl);
    const uint32_t sj_h = smem_u32(sJh), sj_l = smem_u32(sJl);

    for (int kb = 0; kb < CCH; kb += 64) {
        __syncthreads();
        for (int idx = t; idx < 128 * 8; idx += 256) {
            int r = idx >> 3, c = idx & 7;
            *(uint4*)(sIh + r * XST + c * 8) =
                *(const uint4*)(Xbh + (size_t)(i0 + r) * CCH + kb + c * 8);
            *(uint4*)(sIl + r * XST + c * 8) =
                *(const uint4*)(Xbl + (size_t)(i0 + r) * CCH + kb + c * 8);
            *(uint4*)(sJh + r * XST + c * 8) =
                *(const uint4*)(Xbh + (size_t)(j0 + r) * CCH + kb + c * 8);
            *(uint4*)(sJl + r * XST + c * 8) =
                *(const uint4*)(Xbl + (size_t)(j0 + r) * CCH + kb + c * 8);
        }
        __syncthreads();
#pragma unroll
        for (int ks = 0; ks < 4; ks++) {
            uint32_t ah[2][4], al[2][4];
#pragma unroll
            for (int mf = 0; mf < 2; mf++) {
                uint32_t off = (uint32_t)((wr * 32 + mf * 16 + aRow) * XST +
                                          ks * 16 + aCol) * 2;
                ldsm4(ah[mf], si_h + off);
                ldsm4(al[mf], si_l + off);
            }
#pragma unroll
            for (int bt = 0; bt < 4; bt++) {
                uint32_t bh[4], bl[4];
                uint32_t off = (uint32_t)((wc * 64 + bt * 16 + bRow) * XST +
                                          ks * 16 + bCol) * 2;
                ldsm4(bh, sj_h + off);
                ldsm4(bl, sj_l + off);
#pragma unroll
                for (int mf = 0; mf < 2; mf++)
#pragma unroll
                    for (int sub = 0; sub < 2; sub++) {
                        mma_bf16(acc[mf][bt * 2 + sub], ah[mf], &bh[sub * 2]);
                        mma_bf16(acc[mf][bt * 2 + sub], ah[mf], &bl[sub * 2]);
                        mma_bf16(acc[mf][bt * 2 + sub], al[mf], &bh[sub * 2]);
                    }
            }
        }
    }

#pragma unroll
    for (int mf = 0; mf < 2; mf++)
#pragma unroll
    for (int nf = 0; nf < 8; nf++)
#pragma unroll
    for (int pr = 0; pr < 2; pr++) {
        int i = i0 + wr * 32 + mf * 16 + (l >> 2) + pr * 8;
        int j = j0 + wc * 64 + nf * 8 + (l & 3) * 2;
        *(float2*)(out + (size_t)b * N * N + (size_t)i * N + j) =
            make_float2(acc[mf][nf][pr * 2 + 0], acc[mf][nf][pr * 2 + 1]);
    }
}

// ---------------------------------------------------------------------------
// Gram 64x64 (att3, fp32)
// ---------------------------------------------------------------------------
__global__ __launch_bounds__(256) void attnt_kernel(
    const float* __restrict__ X, float* __restrict__ out, int N)
{
    __shared__ float Ai[32][65];
    __shared__ float Bj[32][65];
    const int b  = blockIdx.z;
    const int i0 = blockIdx.x * 64, j0 = blockIdx.y * 64;
    const int t  = threadIdx.x;
    const int ty = t >> 4, tx = t & 15;
    const int r0 = ty * 4, c0 = tx * 4;
    const float* Xb = X + (size_t)b * N * CCH;

    float acc[4][4] = {};
    for (int k0 = 0; k0 < CCH; k0 += 32) {
#pragma unroll
        for (int i = 0; i < 8; i++) {
            int lin = t + 256 * i;
            int r = lin >> 5, k = lin & 31;
            Ai[k][r] = Xb[(size_t)(i0 + r) * CCH + k0 + k];
            Bj[k][r] = Xb[(size_t)(j0 + r) * CCH + k0 + k];
        }
        __syncthreads();
#pragma unroll
        for (int k = 0; k < 32; k++) {
            float a[4], bb[4];
#pragma unroll
            for (int i = 0; i < 4; i++) a[i]  = Ai[k][r0 + i];
#pragma unroll
            for (int j = 0; j < 4; j++) bb[j] = Bj[k][c0 + j];
#pragma unroll
            for (int i = 0; i < 4; i++)
#pragma unroll
                for (int j = 0; j < 4; j++)
                    acc[i][j] += a[i] * bb[j];
        }
        __syncthreads();
    }
#pragma unroll
    for (int i = 0; i < 4; i++) {
        float4 o = make_float4(acc[i][0], acc[i][1], acc[i][2], acc[i][3]);
        *(float4*)&out[(size_t)b * N * N + (size_t)(i0 + r0 + i) * N + j0 + c0] = o;
    }
}

// ---------------------------------------------------------------------------
// Fused sigmoid-attention: m-tile 64 rows x FULL 256 ch, single-staged K.
// 8 warps: wn = w&3 (16 n-rows), wc = w>>2 (m-col half / ch half).
// ---------------------------------------------------------------------------
#define KST 264
#define SST 72

__global__ __launch_bounds__(256, 1) void fused_mma_kernel(
    const __nv_bfloat16* __restrict__ xh, const __nv_bfloat16* __restrict__ xl,
    const float* __restrict__ p1,
    const float* __restrict__ att2, const float* __restrict__ att3,
    const float* __restrict__ pa1, const float* __restrict__ pa2,
    const float* __restrict__ pa3, float* __restrict__ out)
{
    extern __shared__ char smbuf[];
    __nv_bfloat16* Qh = (__nv_bfloat16*)smbuf;          // 64 x 264
    __nv_bfloat16* Ql = Qh + 64 * KST;
    __nv_bfloat16* Kh = Ql + 64 * KST;                  // 64 x 264 (full 256 ch)
    __nv_bfloat16* Kl = Kh + 64 * KST;
    __nv_bfloat16* Sh = Kl + 64 * KST;                  // 64 x 72
    __nv_bfloat16* Sl = Sh + 64 * SST;
    float* A2s = (float*)(Sl + 64 * SST);               // 17 x 257
    float* A3s = A2s + 17 * 257;                        // 5 x 65

    const int b  = blockIdx.y;
    const int n0 = blockIdx.x * 64;
    const int t  = threadIdx.x, w = t >> 5, l = t & 31;
    const int wn = w & 3, wc = w >> 2;
    const int aRow = l & 15, aCol = (l >> 4) * 8;
    const int bRow = (l >> 4) * 8 + (l & 7);
    const int bCol = ((l >> 3) & 1) * 8;

    const __nv_bfloat16* Xh = xh + (size_t)b * N1D * CCH;
    const __nv_bfloat16* Xl = xl + (size_t)b * N1D * CCH;
    const float sa1 = *pa1, sa2 = *pa2, sa3 = *pa3;
    const int r2lo = n0 >> 2, r3lo = n0 >> 4;

    // ---- stage Q (64 x 256 hi/lo) ----
#pragma unroll
    for (int i = 0; i < 8; i++) {
        int idx = t + 256 * i;               // 2048 = 64 rows x 32 chunks
        int r = idx >> 5, c = idx & 31;
        *(uint4*)(Qh + r * KST + c * 8) =
            *(const uint4*)(Xh + (size_t)(n0 + r) * CCH + c * 8);
        *(uint4*)(Ql + r * KST + c * 8) =
            *(const uint4*)(Xl + (size_t)(n0 + r) * CCH + c * 8);
    }
    // ---- gating windows ----
    for (int i = t; i < 17 * 256; i += 256) {
        int rr = i >> 8, cc = i & 255;
        A2s[rr * 257 + cc] = att2[((size_t)b * 256 + min(r2lo + rr, 255)) * 256 + cc];
    }
    for (int i = t; i < 5 * 64; i += 256) {
        int rr = i >> 6, cc = i & 63;
        A3s[rr * 65 + cc] = att3[((size_t)b * 64 + min(r3lo + rr, 63)) * 64 + cc];
    }

    const uint32_t qh0 = smem_u32(Qh), ql0 = smem_u32(Ql);
    const uint32_t kh0 = smem_u32(Kh), kl0 = smem_u32(Kl);
    const uint32_t sh0 = smem_u32(Sh), sl0 = smem_u32(Sl);

    // gating constants for this thread's 2 S-rows
    const float *R0p[2], *R1p[2], *T0p[2], *T1p[2];
    float fnv[2], fn3v[2];
#pragma unroll
    for (int pr = 0; pr < 2; pr++) {
        int n = n0 + wn * 16 + (l >> 2) + pr * 8;
        int rn = n >> 2;
        fnv[pr] = (float)(n & 3) * 0.25f;
        R0p[pr] = A2s + (rn - r2lo) * 257;
        R1p[pr] = A2s + (min(rn + 1, 255) - r2lo) * 257;
        int rn3 = n >> 4;
        fn3v[pr] = (float)(n & 15) * 0.0625f;
        T0p[pr] = A3s + (rn3 - r3lo) * 65;
        T1p[pr] = A3s + (min(rn3 + 1, 63) - r3lo) * 65;
    }

    float O[16][4];
#pragma unroll
    for (int f = 0; f < 16; f++)
#pragma unroll
        for (int e = 0; e < 4; e++) O[f][e] = 0.f;

    for (int mt = 0; mt < 16; mt++) {
        const int m0 = mt * 64;
        __syncthreads();                     // prior GEMM2 done reading K/S
        // ---- stage K tile (64 rows x 256 ch hi/lo) ----
#pragma unroll
        for (int i = 0; i < 8; i++) {
            int idx = t + 256 * i;
            int r = idx >> 5, c = idx & 31;
            *(uint4*)(Kh + r * KST + c * 8) =
                *(const uint4*)(Xh + (size_t)(m0 + r) * CCH + c * 8);
            *(uint4*)(Kl + r * KST + c * 8) =
                *(const uint4*)(Xl + (size_t)(m0 + r) * CCH + c * 8);
        }
        __syncthreads();

        // ---- GEMM1: S(64x64) = Q . K^T over all 256 ch ----
        float Sa[4][4];
#pragma unroll
        for (int nf = 0; nf < 4; nf++)
#pragma unroll
            for (int e = 0; e < 4; e++) Sa[nf][e] = 0.f;

#pragma unroll
        for (int kc = 0; kc < 16; kc++) {
            uint32_t ah[4], al[4];
            uint32_t offA = (uint32_t)((wn * 16 + aRow) * KST + kc * 16 + aCol) * 2;
            ldsm4(ah, qh0 + offA);
            ldsm4(al, ql0 + offA);
#pragma unroll
            for (int bt = 0; bt < 2; bt++) {
                uint32_t rh[4], rl[4];
                uint32_t offB = (uint32_t)((wc * 32 + bt * 16 + bRow) * KST +
                                           kc * 16 + bCol) * 2;
                ldsm4(rh, kh0 + offB);
                ldsm4(rl, kl0 + offB);
                mma_bf16(Sa[bt * 2],     ah, &rh[0]);
                mma_bf16(Sa[bt * 2],     ah, &rl[0]);
                mma_bf16(Sa[bt * 2],     al, &rh[0]);
                mma_bf16(Sa[bt * 2 + 1], ah, &rh[2]);
                mma_bf16(Sa[bt * 2 + 1], ah, &rl[2]);
                mma_bf16(Sa[bt * 2 + 1], al, &rh[2]);
            }
        }

        // ---- epilogue: gating + sigmoid -> Sh/Sl ----
#pragma unroll
        for (int nf = 0; nf < 4; nf++)
#pragma unroll
        for (int pr = 0; pr < 2; pr++) {
            const int row_l = wn * 16 + (l >> 2) + pr * 8;
            const int col_l = wc * 32 + nf * 8 + (l & 3) * 2;
            const float fn = fnv[pr], fn3 = fn3v[pr];
            const float *R0 = R0p[pr], *R1 = R1p[pr];
            const float *T0 = T0p[pr], *T1 = T1p[pr];
            __nv_bfloat16 hh[2], hl[2];
#pragma unroll
            for (int e = 0; e < 2; e++) {
                int m = m0 + col_l + e;
                float Sv = Sa[nf][pr * 2 + e];
                int cm = m >> 2;
                float fm = (float)(m & 3) * 0.25f;
                int cm1 = min(cm + 1, 255);
                float v2 = (1.f - fn) * ((1.f - fm) * R0[cm] + fm * R0[cm1]) +
                           fn         * ((1.f - fm) * R1[cm] + fm * R1[cm1]);
                int cm3 = m >> 4;
                float fm3 = (float)(m & 15) * 0.0625f;
                int cm31 = min(cm3 + 1, 63);
                float v3 = (1.f - fn3) * ((1.f - fm3) * T0[cm3] + fm3 * T0[cm31]) +
                           fn3         * ((1.f - fm3) * T1[cm3] + fm3 * T1[cm31]);
                float val = sa1 * Sv + sa2 * v2 + sa3 * v3;
                float sg = 1.0f / (1.0f + __expf(-val));
                hh[e] = __float2bfloat16_rn(sg);
                hl[e] = __float2bfloat16_rn(sg - __bfloat162float(hh[e]));
            }
            *(uint32_t*)&Sh[row_l * SST + col_l] = pack_bf16(hh[0], hh[1]);
            *(uint32_t*)&Sl[row_l * SST + col_l] = pack_bf16(hl[0], hl[1]);
        }
        __syncthreads();                     // S visible

        // ---- GEMM2: O(64x256) += S(64x64) . K(64x256) ----
#pragma unroll
        for (int kc = 0; kc < 4; kc++) {
            uint32_t sAh[4], sAl[4];
            uint32_t offA = (uint32_t)((wn * 16 + aRow) * SST + kc * 16 + aCol) * 2;
            ldsm4(sAh, sh0 + offA);
            ldsm4(sAl, sl0 + offA);
#pragma unroll
            for (int p = 0; p < 8; p++) {
                uint32_t rh[4], rl[4];
                uint32_t offB = (uint32_t)((kc * 16 + aRow) * KST +
                                           wc * 128 + p * 16 + aCol) * 2;
                ldsm4t(rh, kh0 + offB);
                ldsm4t(rl, kl0 + offB);
                mma_bf16(O[p * 2],     sAh, &rh[0]);
                mma_bf16(O[p * 2],     sAh, &rl[0]);
                mma_bf16(O[p * 2],     sAl, &rh[0]);
                mma_bf16(O[p * 2 + 1], sAh, &rh[2]);
                mma_bf16(O[p * 2 + 1], sAh, &rl[2]);
                mma_bf16(O[p * 2 + 1], sAl, &rh[2]);
            }
        }
    }

    // ---- final: out = O + p1 ----
#pragma unroll
    for (int f = 0; f < 16; f++)
#pragma unroll
    for (int pr = 0; pr < 2; pr++) {
        const int n  = n0 + wn * 16 + (l >> 2) + pr * 8;
        const int ch = wc * 128 + f * 8 + (l & 3) * 2;
        const size_t o = ((size_t)(b * N1D + n)) * CCH + ch;
        float2 pv = *(const float2*)(p1 + o);
        *(float2*)(out + o) = make_float2(O[f][pr * 2 + 0] + pv.x,
                                          O[f][pr * 2 + 1] + pv.y);
    }
}

// ---------------------------------------------------------------------------
extern "C" void kernel_launch(void* const* d_in, const int* in_sizes, int n_in,
                              void* d_out, int out_size)
{
    const float* f1 = (const float*)d_in[0];
    const float* f2 = (const float*)d_in[1];
    const float* f3 = (const float*)d_in[2];
    const float* w1 = (const float*)d_in[3];
    const float* b1 = (const float*)d_in[4];
    const float* w2 = (const float*)d_in[5];
    const float* b2 = (const float*)d_in[6];
    const float* w3 = (const float*)d_in[7];
    const float* b3 = (const float*)d_in[8];
    const float* a1 = (const float*)d_in[9];
    const float* a2 = (const float*)d_in[10];
    const float* a3 = (const float*)d_in[11];
    float* out = (float*)d_out;

    float *p1, *x3, *att2, *att3;
    __nv_bfloat16 *x1h, *x1l, *x2h, *x2l;
    __nv_bfloat16 *f1h, *f1l, *f2h, *f2l, *f3h, *f3l;
    __nv_bfloat16 *w1h, *w1l, *w2h, *w2l, *w3h, *w3l;
    cudaGetSymbolAddress((void**)&p1,   g_p1);
    cudaGetSymbolAddress((void**)&x3,   g_x3);
    cudaGetSymbolAddress((void**)&att2, g_att2);
    cudaGetSymbolAddress((void**)&att3, g_att3);
    cudaGetSymbolAddress((void**)&x1h,  g_x1h);
    cudaGetSymbolAddress((void**)&x1l,  g_x1l);
    cudaGetSymbolAddress((void**)&x2h,  g_x2h);
    cudaGetSymbolAddress((void**)&x2l,  g_x2l);
    cudaGetSymbolAddress((void**)&f1h,  g_f1h);
    cudaGetSymbolAddress((void**)&f1l,  g_f1l);
    cudaGetSymbolAddress((void**)&f2h,  g_f2h);
    cudaGetSymbolAddress((void**)&f2l,  g_f2l);
    cudaGetSymbolAddress((void**)&f3h,  g_f3h);
    cudaGetSymbolAddress((void**)&f3l,  g_f3l);
    cudaGetSymbolAddress((void**)&w1h,  g_w1h);
    cudaGetSymbolAddress((void**)&w1l,  g_w1l);
    cudaGetSymbolAddress((void**)&w2h,  g_w2h);
    cudaGetSymbolAddress((void**)&w2l,  g_w2l);
    cudaGetSymbolAddress((void**)&w3h,  g_w3h);
    cudaGetSymbolAddress((void**)&w3l,  g_w3l);

    split_kernel<<<(BATCH * N1D * CCH) / 1024, 256>>>(f1, f1h, f1l);
    split_kernel<<<(BATCH * 256 * 512) / 1024, 256>>>(f2, f2h, f2l);
    split_kernel<<<(BATCH * 64 * 1024) / 1024, 256>>>(f3, f3h, f3l);
    split_kernel<<<(256 * 256)   / 1024, 256>>>(w1, w1h, w1l);
    split_kernel<<<(512 * 256)   / 1024, 256>>>(w2, w2h, w2l);
    split_kernel<<<(1024 * 256)  / 1024, 256>>>(w3, w3h, w3l);

    init_bias_kernel<<<(BATCH * 64 * CCH) / 1024, 256>>>(x3, b3);

    const int smemP128 = (128 * 72 * 2 + 64 * 264 * 2) * 2;
    const int smemP64  = (64  * 72 * 2 + 64 * 264 * 2) * 2;
    cudaFuncSetAttribute(proj_mma_kernel<128>,
                         cudaFuncAttributeMaxDynamicSharedMemorySize, smemP128);
    cudaFuncSetAttribute(proj_mma_kernel<64>,
                         cudaFuncAttributeMaxDynamicSharedMemorySize, smemP64);

    proj_mma_kernel<128><<<dim3(128, 1), 256, smemP128>>>(
        f1h, f1l, w1h, w1l, b1, 256, p1, 0, x1h, x1l);
    proj_mma_kernel<64><<<dim3(64, 1), 256, smemP64>>>(
        f2h, f2l, w2h, w2l, b2, 512, nullptr, 0, x2h, x2l);
    proj_mma_kernel<64><<<dim3(16, 4), 256, smemP64>>>(
        f3h, f3l, w3h, w3l, b3, 1024, x3, 1, nullptr, nullptr);

    const int smemG = 4 * 128 * 72 * 2;
    cudaFuncSetAttribute(gram_mma_kernel,
                         cudaFuncAttributeMaxDynamicSharedMemorySize, smemG);
    gram_mma_kernel<<<dim3(2, 2, BATCH), 256, smemG>>>(x2h, x2l, att2, 256);

    attnt_kernel<<<dim3(1, 1, BATCH), 256>>>(x3, att3, 64);

    // Q(64x264 h/l) + K(64x264 h/l) + S(64x72 h/l) in bf16, + fp32 gating
    const int smemF = (64 * KST * 2 + 64 * KST * 2 + 64 * SST * 2) * 2
                      + (17 * 257 + 5 * 65) * 4;
    cudaFuncSetAttribute(fused_mma_kernel,
                         cudaFuncAttributeMaxDynamicSharedMemorySize, smemF);
    fused_mma_kernel<<<dim3(16, BATCH), 256, smemF>>>(
        x1h, x1l, p1, att2, att3, a1, a2, a3, out);
}

// round 10
// speedup vs baseline: 1.6125x; 1.5010x over previous
#include <cuda_runtime.h>
#include <cuda_fp16.h>
#include <math.h>
#include <stdint.h>

#define BATCH 16
#define N1D 1024
#define CCH 256

// ---------------- device scratch ----------------
__device__ float g_p1[BATCH * N1D * CCH];
__device__ float g_x3[BATCH * 64 * CCH];
__device__ float g_att2[BATCH * 256 * 256];
__device__ float g_att3[BATCH * 64 * 64];
__device__ __half g_x1[BATCH * N1D * CCH];
__device__ __half g_x2[BATCH * 256 * CCH];
__device__ __half g_f1[BATCH * N1D * CCH];
__device__ __half g_f2[BATCH * 256 * 512];
__device__ __half g_f3[BATCH * 64 * 1024];
__device__ __half g_w1[256 * 256];
__device__ __half g_w2[512 * 256];
__device__ __half g_w3[1024 * 256];

// ---------------- warp-MMA helpers ----------------
__device__ __forceinline__ uint32_t smem_u32(const void* p) {
    uint32_t a;
    asm("{ .reg .u64 t; cvta.to.shared.u64 t, %1; cvt.u32.u64 %0, t; }"
        : "=r"(a) : "l"(p));
    return a;
}
__device__ __forceinline__ void ldsm4(uint32_t* r, uint32_t a) {
    asm volatile("ldmatrix.sync.aligned.m8n8.x4.shared.b16 {%0,%1,%2,%3}, [%4];"
        : "=r"(r[0]), "=r"(r[1]), "=r"(r[2]), "=r"(r[3]) : "r"(a));
}
__device__ __forceinline__ void ldsm4t(uint32_t* r, uint32_t a) {
    asm volatile("ldmatrix.sync.aligned.m8n8.x4.trans.shared.b16 {%0,%1,%2,%3}, [%4];"
        : "=r"(r[0]), "=r"(r[1]), "=r"(r[2]), "=r"(r[3]) : "r"(a));
}
__device__ __forceinline__ void mma_f16(float* d, const uint32_t* a,
                                        const uint32_t* b) {
    asm volatile(
        "mma.sync.aligned.m16n8k16.row.col.f32.f16.f16.f32 "
        "{%0,%1,%2,%3}, {%4,%5,%6,%7}, {%8,%9}, {%0,%1,%2,%3};"
        : "+f"(d[0]), "+f"(d[1]), "+f"(d[2]), "+f"(d[3])
        : "r"(a[0]), "r"(a[1]), "r"(a[2]), "r"(a[3]), "r"(b[0]), "r"(b[1]));
}
__device__ __forceinline__ unsigned pack_h(__half a, __half b) {
    return ((unsigned)__half_as_ushort(b) << 16) | (unsigned)__half_as_ushort(a);
}

// ---------------------------------------------------------------------------
// ONE conversion kernel: fp32 -> fp16 for all 6 input tensors
// block ranges (1024 elems each): f1 4096 | f2 2048 | f3 1024 | w1 64 | w2 128 | w3 256
// ---------------------------------------------------------------------------
__global__ void cvt_all_kernel(
    const float* __restrict__ f1, const float* __restrict__ f2,
    const float* __restrict__ f3, const float* __restrict__ w1,
    const float* __restrict__ w2, const float* __restrict__ w3,
    __half* __restrict__ o1, __half* __restrict__ o2, __half* __restrict__ o3,
    __half* __restrict__ o4, __half* __restrict__ o5, __half* __restrict__ o6)
{
    int bi = blockIdx.x;
    const float* src; __half* dst; int base;
    if      (bi < 4096) { src = f1; dst = o1; base = 0; }
    else if (bi < 6144) { src = f2; dst = o2; base = 4096; }
    else if (bi < 7168) { src = f3; dst = o3; base = 6144; }
    else if (bi < 7232) { src = w1; dst = o4; base = 7168; }
    else if (bi < 7360) { src = w2; dst = o5; base = 7232; }
    else                { src = w3; dst = o6; base = 7360; }
    size_t i4 = (size_t)(bi - base) * 256 + threadIdx.x;
    float4 v = *(const float4*)(src + i4 * 4);
    uint2 o;
    o.x = pack_h(__float2half_rn(v.x), __float2half_rn(v.y));
    o.y = pack_h(__float2half_rn(v.z), __float2half_rn(v.w));
    *(uint2*)(dst + i4 * 4) = o;
}

__global__ void init_bias_kernel(float* __restrict__ out,
                                 const float* __restrict__ bias)
{
    int idx = blockIdx.x * 256 + threadIdx.x;
    int cj = idx & 63;
    float4 bv = *(const float4*)&bias[cj * 4];
    *(float4*)&out[idx * 4] = bv;
}

// ---------------------------------------------------------------------------
// Projection via warp MMA (fp16): out[M,256] = A[M,K] @ W[K,256] + b
// ---------------------------------------------------------------------------
template<int MT>
__global__ __launch_bounds__(256) void proj_mma_kernel(
    const __half* __restrict__ A, const __half* __restrict__ W,
    const float* __restrict__ bias, int KDIM,
    float* __restrict__ outF, int atomicF, __half* __restrict__ outH)
{
    constexpr int NRW  = MT / 32;
    constexpr int NCW  = 8 / NRW;
    constexpr int WCOL = 256 / NCW;
    constexpr int NF   = WCOL / 8;
    constexpr int NP   = WCOL / 16;
    constexpr int AST  = 72, WST = 264;

    extern __shared__ char smbuf[];
    __half* sA = (__half*)smbuf;
    __half* sW = sA + MT * AST;

    const int t = threadIdx.x, w = t >> 5, l = t & 31;
    const int wr = w / NCW, wc = w % NCW;
    const int aRow = l & 15, aCol = (l >> 4) * 8;
    const int row0 = blockIdx.x * MT;
    const int kd  = KDIM / gridDim.y;
    const int kb0 = blockIdx.y * kd;

    float acc[2][NF][4];
#pragma unroll
    for (int mf = 0; mf < 2; mf++)
#pragma unroll
        for (int nf = 0; nf < NF; nf++)
#pragma unroll
            for (int e = 0; e < 4; e++) acc[mf][nf][e] = 0.f;

    const uint32_t sa0 = smem_u32(sA), sw0 = smem_u32(sW);

    for (int kb = 0; kb < kd; kb += 64) {
        const int kg = kb0 + kb;
        __syncthreads();
        for (int idx = t; idx < MT * 8; idx += 256) {
            int r = idx >> 3, c = idx & 7;
            *(uint4*)(sA + r * AST + c * 8) =
                *(const uint4*)(A + (size_t)(row0 + r) * KDIM + kg + c * 8);
        }
        for (int idx = t; idx < 64 * 32; idx += 256) {
            int r = idx >> 5, c = idx & 31;
            *(uint4*)(sW + r * WST + c * 8) =
                *(const uint4*)(W + (size_t)(kg + r) * 256 + c * 8);
        }
        __syncthreads();
#pragma unroll
        for (int ks = 0; ks < 4; ks++) {
            uint32_t a[2][4];
#pragma unroll
            for (int mf = 0; mf < 2; mf++) {
                uint32_t off = (uint32_t)((wr * 32 + mf * 16 + aRow) * AST +
                                          ks * 16 + aCol) * 2;
                ldsm4(a[mf], sa0 + off);
            }
#pragma unroll
            for (int p = 0; p < NP; p++) {
                uint32_t bfr[4];
                uint32_t off = (uint32_t)((ks * 16 + aRow) * WST +
                                          wc * WCOL + p * 16 + aCol) * 2;
                ldsm4t(bfr, sw0 + off);
#pragma unroll
                for (int mf = 0; mf < 2; mf++) {
                    mma_f16(acc[mf][p * 2 + 0], a[mf], &bfr[0]);
                    mma_f16(acc[mf][p * 2 + 1], a[mf], &bfr[2]);
                }
            }
        }
    }

#pragma unroll
    for (int mf = 0; mf < 2; mf++)
#pragma unroll
    for (int nf = 0; nf < NF; nf++)
#pragma unroll
    for (int pr = 0; pr < 2; pr++) {
        int r = row0 + wr * 32 + mf * 16 + (l >> 2) + pr * 8;
        int c = wc * WCOL + nf * 8 + (l & 3) * 2;
        float v0 = acc[mf][nf][pr * 2 + 0];
        float v1 = acc[mf][nf][pr * 2 + 1];
        if (atomicF) {
            atomicAdd(outF + (size_t)r * 256 + c,     v0);
            atomicAdd(outF + (size_t)r * 256 + c + 1, v1);
        } else {
            v0 += bias[c]; v1 += bias[c + 1];
            if (outF) *(float2*)(outF + (size_t)r * 256 + c) = make_float2(v0, v1);
            if (outH)
                *(uint32_t*)(outH + (size_t)r * 256 + c) =
                    pack_h(__float2half_rn(v0), __float2half_rn(v1));
        }
    }
}

// ---------------------------------------------------------------------------
// Gram att2 via warp MMA (NT, fp16): out[b] = X.X^T, X [256,256]
// ---------------------------------------------------------------------------
__global__ __launch_bounds__(256) void gram_mma_kernel(
    const __half* __restrict__ X, float* __restrict__ out, int N)
{
    constexpr int XST = 72;
    extern __shared__ char smbuf[];
    __half* sI = (__half*)smbuf;
    __half* sJ = sI + 128 * XST;

    const int b = blockIdx.z;
    const int i0 = blockIdx.x * 128, j0 = blockIdx.y * 128;
    const int t = threadIdx.x, w = t >> 5, l = t & 31;
    const int wr = w >> 1, wc = w & 1;
    const int aRow = l & 15, aCol = (l >> 4) * 8;
    const int bRow = (l >> 4) * 8 + (l & 7), bCol = ((l >> 3) & 1) * 8;
    const __half* Xb = X + (size_t)b * N * CCH;

    float acc[2][8][4];
#pragma unroll
    for (int mf = 0; mf < 2; mf++)
#pragma unroll
        for (int nf = 0; nf < 8; nf++)
#pragma unroll
            for (int e = 0; e < 4; e++) acc[mf][nf][e] = 0.f;

    const uint32_t si0 = smem_u32(sI), sj0 = smem_u32(sJ);

    for (int kb = 0; kb < CCH; kb += 64) {
        __syncthreads();
        for (int idx = t; idx < 128 * 8; idx += 256) {
            int r = idx >> 3, c = idx & 7;
            *(uint4*)(sI + r * XST + c * 8) =
                *(const uint4*)(Xb + (size_t)(i0 + r) * CCH + kb + c * 8);
            *(uint4*)(sJ + r * XST + c * 8) =
                *(const uint4*)(Xb + (size_t)(j0 + r) * CCH + kb + c * 8);
        }
        __syncthreads();
#pragma unroll
        for (int ks = 0; ks < 4; ks++) {
            uint32_t a[2][4];
#pragma unroll
            for (int mf = 0; mf < 2; mf++) {
                uint32_t off = (uint32_t)((wr * 32 + mf * 16 + aRow) * XST +
                                          ks * 16 + aCol) * 2;
                ldsm4(a[mf], si0 + off);
            }
#pragma unroll
            for (int bt = 0; bt < 4; bt++) {
                uint32_t bfr[4];
                uint32_t off = (uint32_t)((wc * 64 + bt * 16 + bRow) * XST +
                                          ks * 16 + bCol) * 2;
                ldsm4(bfr, sj0 + off);
#pragma unroll
                for (int mf = 0; mf < 2; mf++) {
                    mma_f16(acc[mf][bt * 2 + 0], a[mf], &bfr[0]);
                    mma_f16(acc[mf][bt * 2 + 1], a[mf], &bfr[2]);
                }
            }
        }
    }

#pragma unroll
    for (int mf = 0; mf < 2; mf++)
#pragma unroll
    for (int nf = 0; nf < 8; nf++)
#pragma unroll
    for (int pr = 0; pr < 2; pr++) {
        int i = i0 + wr * 32 + mf * 16 + (l >> 2) + pr * 8;
        int j = j0 + wc * 64 + nf * 8 + (l & 3) * 2;
        *(float2*)(out + (size_t)b * N * N + (size_t)i * N + j) =
            make_float2(acc[mf][nf][pr * 2 + 0], acc[mf][nf][pr * 2 + 1]);
    }
}

// ---------------------------------------------------------------------------
// Gram 64x64 (att3, fp32)
// ---------------------------------------------------------------------------
__global__ __launch_bounds__(256) void attnt_kernel(
    const float* __restrict__ X, float* __restrict__ out, int N)
{
    __shared__ float Ai[32][65];
    __shared__ float Bj[32][65];
    const int b  = blockIdx.z;
    const int i0 = blockIdx.x * 64, j0 = blockIdx.y * 64;
    const int t  = threadIdx.x;
    const int ty = t >> 4, tx = t & 15;
    const int r0 = ty * 4, c0 = tx * 4;
    const float* Xb = X + (size_t)b * N * CCH;

    float acc[4][4] = {};
    for (int k0 = 0; k0 < CCH; k0 += 32) {
#pragma unroll
        for (int i = 0; i < 8; i++) {
            int lin = t + 256 * i;
            int r = lin >> 5, k = lin & 31;
            Ai[k][r] = Xb[(size_t)(i0 + r) * CCH + k0 + k];
            Bj[k][r] = Xb[(size_t)(j0 + r) * CCH + k0 + k];
        }
        __syncthreads();
#pragma unroll
        for (int k = 0; k < 32; k++) {
            float a[4], bb[4];
#pragma unroll
            for (int i = 0; i < 4; i++) a[i]  = Ai[k][r0 + i];
#pragma unroll
            for (int j = 0; j < 4; j++) bb[j] = Bj[k][c0 + j];
#pragma unroll
            for (int i = 0; i < 4; i++)
#pragma unroll
                for (int j = 0; j < 4; j++)
                    acc[i][j] += a[i] * bb[j];
        }
        __syncthreads();
    }
#pragma unroll
    for (int i = 0; i < 4; i++) {
        float4 o = make_float4(acc[i][0], acc[i][1], acc[i][2], acc[i][3]);
        *(float4*)&out[(size_t)b * N * N + (size_t)(i0 + r0 + i) * N + j0 + c0] = o;
    }
}

// ---------------------------------------------------------------------------
// Fused sigmoid-attention (fp16 single): m-tile 64 x 256 ch, single-staged.
// 8 warps: wn = w&3 (16 n-rows), wc = w>>2 (m half / ch half).
// ---------------------------------------------------------------------------
#define KST 264
#define SST 72

__global__ __launch_bounds__(256) void fused_mma_kernel(
    const __half* __restrict__ x1,
    const float* __restrict__ p1,
    const float* __restrict__ att2, const float* __restrict__ att3,
    const float* __restrict__ pa1, const float* __restrict__ pa2,
    const float* __restrict__ pa3, float* __restrict__ out)
{
    extern __shared__ char smbuf[];
    __half* Qs = (__half*)smbuf;            // 64 x 264
    __half* Ks = Qs + 64 * KST;             // 64 x 264
    __half* Ss = Ks + 64 * KST;             // 64 x 72
    float* A2s = (float*)(Ss + 64 * SST);   // 17 x 257
    float* A3s = A2s + 17 * 257;            // 5 x 65

    const int b  = blockIdx.y;
    const int n0 = blockIdx.x * 64;
    const int t  = threadIdx.x, w = t >> 5, l = t & 31;
    const int wn = w & 3, wc = w >> 2;
    const int aRow = l & 15, aCol = (l >> 4) * 8;
    const int bRow = (l >> 4) * 8 + (l & 7);
    const int bCol = ((l >> 3) & 1) * 8;

    const __half* Xb = x1 + (size_t)b * N1D * CCH;
    const float sa1 = *pa1, sa2 = *pa2, sa3 = *pa3;
    const int r2lo = n0 >> 2, r3lo = n0 >> 4;

    // ---- stage Q (64 x 256) ----
#pragma unroll
    for (int i = 0; i < 8; i++) {
        int idx = t + 256 * i;               // 2048 = 64 rows x 32 chunks
        int r = idx >> 5, c = idx & 31;
        *(uint4*)(Qs + r * KST + c * 8) =
            *(const uint4*)(Xb + (size_t)(n0 + r) * CCH + c * 8);
    }
    // ---- gating windows ----
    for (int i = t; i < 17 * 256; i += 256) {
        int rr = i >> 8, cc = i & 255;
        A2s[rr * 257 + cc] = att2[((size_t)b * 256 + min(r2lo + rr, 255)) * 256 + cc];
    }
    for (int i = t; i < 5 * 64; i += 256) {
        int rr = i >> 6, cc = i & 63;
        A3s[rr * 65 + cc] = att3[((size_t)b * 64 + min(r3lo + rr, 63)) * 64 + cc];
    }

    const uint32_t q0 = smem_u32(Qs);
    const uint32_t k0 = smem_u32(Ks);
    const uint32_t s0 = smem_u32(Ss);

    const float *R0p[2], *R1p[2], *T0p[2], *T1p[2];
    float fnv[2], fn3v[2];
#pragma unroll
    for (int pr = 0; pr < 2; pr++) {
        int n = n0 + wn * 16 + (l >> 2) + pr * 8;
        int rn = n >> 2;
        fnv[pr] = (float)(n & 3) * 0.25f;
        R0p[pr] = A2s + (rn - r2lo) * 257;
        R1p[pr] = A2s + (min(rn + 1, 255) - r2lo) * 257;
        int rn3 = n >> 4;
        fn3v[pr] = (float)(n & 15) * 0.0625f;
        T0p[pr] = A3s + (rn3 - r3lo) * 65;
        T1p[pr] = A3s + (min(rn3 + 1, 63) - r3lo) * 65;
    }

    float O[16][4];
#pragma unroll
    for (int f = 0; f < 16; f++)
#pragma unroll
        for (int e = 0; e < 4; e++) O[f][e] = 0.f;

    for (int mt = 0; mt < 16; mt++) {
        const int m0 = mt * 64;
        __syncthreads();                     // prior GEMM2 done reading K/S
#pragma unroll
        for (int i = 0; i < 8; i++) {        // stage K (64 x 256)
            int idx = t + 256 * i;
            int r = idx >> 5, c = idx & 31;
            *(uint4*)(Ks + r * KST + c * 8) =
                *(const uint4*)(Xb + (size_t)(m0 + r) * CCH + c * 8);
        }
        __syncthreads();

        // ---- GEMM1: S(64x64) = Q . K^T ----
        float Sa[4][4];
#pragma unroll
        for (int nf = 0; nf < 4; nf++)
#pragma unroll
            for (int e = 0; e < 4; e++) Sa[nf][e] = 0.f;

#pragma unroll
        for (int kc = 0; kc < 16; kc++) {
            uint32_t a[4];
            uint32_t offA = (uint32_t)((wn * 16 + aRow) * KST + kc * 16 + aCol) * 2;
            ldsm4(a, q0 + offA);
#pragma unroll
            for (int bt = 0; bt < 2; bt++) {
                uint32_t r[4];
                uint32_t offB = (uint32_t)((wc * 32 + bt * 16 + bRow) * KST +
                                           kc * 16 + bCol) * 2;
                ldsm4(r, k0 + offB);
                mma_f16(Sa[bt * 2 + 0], a, &r[0]);
                mma_f16(Sa[bt * 2 + 1], a, &r[2]);
            }
        }

        // ---- epilogue: gating + sigmoid -> Ss ----
#pragma unroll
        for (int nf = 0; nf < 4; nf++)
#pragma unroll
        for (int pr = 0; pr < 2; pr++) {
            const int row_l = wn * 16 + (l >> 2) + pr * 8;
            const int col_l = wc * 32 + nf * 8 + (l & 3) * 2;
            const float fn = fnv[pr], fn3 = fn3v[pr];
            const float *R0 = R0p[pr], *R1 = R1p[pr];
            const float *T0 = T0p[pr], *T1 = T1p[pr];
            __half hv[2];
#pragma unroll
            for (int e = 0; e < 2; e++) {
                int m = m0 + col_l + e;
                float Sv = Sa[nf][pr * 2 + e];
                int cm = m >> 2;
                float fm = (float)(m & 3) * 0.25f;
                int cm1 = min(cm + 1, 255);
                float v2 = (1.f - fn) * ((1.f - fm) * R0[cm] + fm * R0[cm1]) +
                           fn         * ((1.f - fm) * R1[cm] + fm * R1[cm1]);
                int cm3 = m >> 4;
                float fm3 = (float)(m & 15) * 0.0625f;
                int cm31 = min(cm3 + 1, 63);
                float v3 = (1.f - fn3) * ((1.f - fm3) * T0[cm3] + fm3 * T0[cm31]) +
                           fn3         * ((1.f - fm3) * T1[cm3] + fm3 * T1[cm31]);
                float val = sa1 * Sv + sa2 * v2 + sa3 * v3;
                float sg = 1.0f / (1.0f + __expf(-val));
                hv[e] = __float2half_rn(sg);
            }
            *(uint32_t*)&Ss[row_l * SST + col_l] = pack_h(hv[0], hv[1]);
        }
        __syncthreads();                     // S visible

        // ---- GEMM2: O(64x256) += S(64x64) . K(64x256) ----
#pragma unroll
        for (int kc = 0; kc < 4; kc++) {
            uint32_t sA[4];
            uint32_t offA = (uint32_t)((wn * 16 + aRow) * SST + kc * 16 + aCol) * 2;
            ldsm4(sA, s0 + offA);
#pragma unroll
            for (int p = 0; p < 8; p++) {
                uint32_t r[4];
                uint32_t offB = (uint32_t)((kc * 16 + aRow) * KST +
                                           wc * 128 + p * 16 + aCol) * 2;
                ldsm4t(r, k0 + offB);
                mma_f16(O[p * 2 + 0], sA, &r[0]);
                mma_f16(O[p * 2 + 1], sA, &r[2]);
            }
        }
    }

    // ---- final: out = O + p1 ----
#pragma unroll
    for (int f = 0; f < 16; f++)
#pragma unroll
    for (int pr = 0; pr < 2; pr++) {
        const int n  = n0 + wn * 16 + (l >> 2) + pr * 8;
        const int ch = wc * 128 + f * 8 + (l & 3) * 2;
        const size_t o = ((size_t)(b * N1D + n)) * CCH + ch;
        float2 pv = *(const float2*)(p1 + o);
        *(float2*)(out + o) = make_float2(O[f][pr * 2 + 0] + pv.x,
                                          O[f][pr * 2 + 1] + pv.y);
    }
}

// ---------------------------------------------------------------------------
extern "C" void kernel_launch(void* const* d_in, const int* in_sizes, int n_in,
                              void* d_out, int out_size)
{
    const float* f1 = (const float*)d_in[0];
    const float* f2 = (const float*)d_in[1];
    const float* f3 = (const float*)d_in[2];
    const float* w1 = (const float*)d_in[3];
    const float* b1 = (const float*)d_in[4];
    const float* w2 = (const float*)d_in[5];
    const float* b2 = (const float*)d_in[6];
    const float* w3 = (const float*)d_in[7];
    const float* b3 = (const float*)d_in[8];
    const float* a1 = (const float*)d_in[9];
    const float* a2 = (const float*)d_in[10];
    const float* a3 = (const float*)d_in[11];
    float* out = (float*)d_out;

    float *p1, *x3, *att2, *att3;
    __half *x1, *x2, *hf1, *hf2, *hf3, *hw1, *hw2, *hw3;
    cudaGetSymbolAddress((void**)&p1,   g_p1);
    cudaGetSymbolAddress((void**)&x3,   g_x3);
    cudaGetSymbolAddress((void**)&att2, g_att2);
    cudaGetSymbolAddress((void**)&att3, g_att3);
    cudaGetSymbolAddress((void**)&x1,   g_x1);
    cudaGetSymbolAddress((void**)&x2,   g_x2);
    cudaGetSymbolAddress((void**)&hf1,  g_f1);
    cudaGetSymbolAddress((void**)&hf2,  g_f2);
    cudaGetSymbolAddress((void**)&hf3,  g_f3);
    cudaGetSymbolAddress((void**)&hw1,  g_w1);
    cudaGetSymbolAddress((void**)&hw2,  g_w2);
    cudaGetSymbolAddress((void**)&hw3,  g_w3);

    // one conversion kernel for all inputs
    cvt_all_kernel<<<7616, 256>>>(f1, f2, f3, w1, w2, w3,
                                  hf1, hf2, hf3, hw1, hw2, hw3);

    init_bias_kernel<<<(BATCH * 64 * CCH) / 1024, 256>>>(x3, b3);

    const int smemP128 = (128 * 72 + 64 * 264) * 2;
    const int smemP64  = (64  * 72 + 64 * 264) * 2;
    cudaFuncSetAttribute(proj_mma_kernel<128>,
                         cudaFuncAttributeMaxDynamicSharedMemorySize, smemP128);
    cudaFuncSetAttribute(proj_mma_kernel<64>,
                         cudaFuncAttributeMaxDynamicSharedMemorySize, smemP64);

    // proj1: p1 fp32 + x1 fp16
    proj_mma_kernel<128><<<dim3(128, 1), 256, smemP128>>>(
        hf1, hw1, b1, 256, p1, 0, x1);
    // proj2: x2 fp16 only
    proj_mma_kernel<64><<<dim3(64, 1), 256, smemP64>>>(
        hf2, hw2, b2, 512, nullptr, 0, x2);
    // proj3: fp32 atomic into bias-preinit x3 (K-split 4)
    proj_mma_kernel<64><<<dim3(16, 4), 256, smemP64>>>(
        hf3, hw3, b3, 1024, x3, 1, nullptr);

    const int smemG = 2 * 128 * 72 * 2;
    cudaFuncSetAttribute(gram_mma_kernel,
                         cudaFuncAttributeMaxDynamicSharedMemorySize, smemG);
    gram_mma_kernel<<<dim3(2, 2, BATCH), 256, smemG>>>(x2, att2, 256);

    attnt_kernel<<<dim3(1, 1, BATCH), 256>>>(x3, att3, 64);

    const int smemF = (64 * KST + 64 * KST + 64 * SST) * 2
                      + (17 * 257 + 5 * 65) * 4;
    cudaFuncSetAttribute(fused_mma_kernel,
                         cudaFuncAttributeMaxDynamicSharedMemorySize, smemF);
    fused_mma_kernel<<<dim3(16, BATCH), 256, smemF>>>(
        x1, p1, att2, att3, a1, a2, a3, out);
}

// round 11
// speedup vs baseline: 2.1567x; 1.3375x over previous
#include <cuda_runtime.h>
#include <cuda_fp16.h>
#include <math.h>
#include <stdint.h>

#define BATCH 16
#define N1D 1024
#define CCH 256

// ---------------- device scratch ----------------
__device__ float g_p1[BATCH * N1D * CCH];
__device__ float g_x3[BATCH * 64 * CCH];
__device__ float g_att2[BATCH * 256 * 256];
__device__ float g_att3[BATCH * 64 * 64];
__device__ __half g_x1[BATCH * N1D * CCH];
__device__ __half g_x2[BATCH * 256 * CCH];
__device__ __half g_f1[BATCH * N1D * CCH];
__device__ __half g_f2[BATCH * 256 * 512];
__device__ __half g_f3[BATCH * 64 * 1024];
__device__ __half g_w1[256 * 256];
__device__ __half g_w2[512 * 256];
__device__ __half g_w3[1024 * 256];

// ---------------- warp-MMA helpers ----------------
__device__ __forceinline__ uint32_t smem_u32(const void* p) {
    uint32_t a;
    asm("{ .reg .u64 t; cvta.to.shared.u64 t, %1; cvt.u32.u64 %0, t; }"
        : "=r"(a) : "l"(p));
    return a;
}
__device__ __forceinline__ void ldsm4(uint32_t* r, uint32_t a) {
    asm volatile("ldmatrix.sync.aligned.m8n8.x4.shared.b16 {%0,%1,%2,%3}, [%4];"
        : "=r"(r[0]), "=r"(r[1]), "=r"(r[2]), "=r"(r[3]) : "r"(a));
}
__device__ __forceinline__ void ldsm4t(uint32_t* r, uint32_t a) {
    asm volatile("ldmatrix.sync.aligned.m8n8.x4.trans.shared.b16 {%0,%1,%2,%3}, [%4];"
        : "=r"(r[0]), "=r"(r[1]), "=r"(r[2]), "=r"(r[3]) : "r"(a));
}
__device__ __forceinline__ void mma_f16(float* d, const uint32_t* a,
                                        const uint32_t* b) {
    asm volatile(
        "mma.sync.aligned.m16n8k16.row.col.f32.f16.f16.f32 "
        "{%0,%1,%2,%3}, {%4,%5,%6,%7}, {%8,%9}, {%0,%1,%2,%3};"
        : "+f"(d[0]), "+f"(d[1]), "+f"(d[2]), "+f"(d[3])
        : "r"(a[0]), "r"(a[1]), "r"(a[2]), "r"(a[3]), "r"(b[0]), "r"(b[1]));
}
__device__ __forceinline__ unsigned pack_h(__half a, __half b) {
    return ((unsigned)__half_as_ushort(b) << 16) | (unsigned)__half_as_ushort(a);
}

// ---------------------------------------------------------------------------
// cvt + bias-init in ONE launch.
// blocks: f1 4096 | f2 2048 | f3 1024 | w1 64 | w2 128 | w3 256 | x3init 256
// ---------------------------------------------------------------------------
__global__ void cvt_all_kernel(
    const float* __restrict__ f1, const float* __restrict__ f2,
    const float* __restrict__ f3, const float* __restrict__ w1,
    const float* __restrict__ w2, const float* __restrict__ w3,
    const float* __restrict__ b3,
    __half* __restrict__ o1, __half* __restrict__ o2, __half* __restrict__ o3,
    __half* __restrict__ o4, __half* __restrict__ o5, __half* __restrict__ o6,
    float* __restrict__ x3)
{
    int bi = blockIdx.x;
    if (bi >= 7616) {   // x3 bias init: 256 blocks
        int idx = (bi - 7616) * 256 + threadIdx.x;
        int cj = idx & 63;
        float4 bv = *(const float4*)&b3[cj * 4];
        *(float4*)&x3[idx * 4] = bv;
        return;
    }
    const float* src; __half* dst; int base;
    if      (bi < 4096) { src = f1; dst = o1; base = 0; }
    else if (bi < 6144) { src = f2; dst = o2; base = 4096; }
    else if (bi < 7168) { src = f3; dst = o3; base = 6144; }
    else if (bi < 7232) { src = w1; dst = o4; base = 7168; }
    else if (bi < 7360) { src = w2; dst = o5; base = 7232; }
    else                { src = w3; dst = o6; base = 7360; }
    size_t i4 = (size_t)(bi - base) * 256 + threadIdx.x;
    float4 v = *(const float4*)(src + i4 * 4);
    uint2 o;
    o.x = pack_h(__float2half_rn(v.x), __float2half_rn(v.y));
    o.y = pack_h(__float2half_rn(v.z), __float2half_rn(v.w));
    *(uint2*)(dst + i4 * 4) = o;
}

// ---------------------------------------------------------------------------
// ALL projections in ONE launch (MT=64, 8 warps: 2 row-warps x 4 col-warps).
// blocks: proj1 0..255 | proj2 256..319 | proj3 320..383 (16 tiles x 4 ksplit)
// ---------------------------------------------------------------------------
__global__ __launch_bounds__(256) void projall_kernel(
    const __half* __restrict__ hf1, const __half* __restrict__ hw1,
    const float* __restrict__ b1, float* __restrict__ p1, __half* __restrict__ x1,
    const __half* __restrict__ hf2, const __half* __restrict__ hw2,
    const float* __restrict__ b2, __half* __restrict__ x2,
    const __half* __restrict__ hf3, const __half* __restrict__ hw3,
    float* __restrict__ x3)
{
    constexpr int AST = 72, WST = 264;
    extern __shared__ char smbuf[];
    __half* sA = (__half*)smbuf;            // 64 x 72
    __half* sW = sA + 64 * AST;             // 64 x 264

    const int bi = blockIdx.x;
    const __half *A, *W; const float* bias = nullptr;
    int KDIM, kbase = 0, kd, row0;
    float* outF = nullptr; __half* outH = nullptr; int atomicF = 0;
    if (bi < 256) {
        A = hf1; W = hw1; bias = b1; KDIM = 256; kd = 256;
        row0 = bi * 64; outF = p1; outH = x1;
    } else if (bi < 320) {
        A = hf2; W = hw2; bias = b2; KDIM = 512; kd = 512;
        row0 = (bi - 256) * 64; outH = x2;
    } else {
        int s = bi - 320;
        A = hf3; W = hw3; KDIM = 1024; kd = 256; kbase = (s >> 4) * 256;
        row0 = (s & 15) * 64; outF = x3; atomicF = 1;
    }

    const int t = threadIdx.x, w = t >> 5, l = t & 31;
    const int wr = w >> 2, wc = w & 3;          // 2 x 4 warp grid
    const int aRow = l & 15, aCol = (l >> 4) * 8;

    float acc[2][8][4];
#pragma unroll
    for (int mf = 0; mf < 2; mf++)
#pragma unroll
        for (int nf = 0; nf < 8; nf++)
#pragma unroll
            for (int e = 0; e < 4; e++) acc[mf][nf][e] = 0.f;

    const uint32_t sa0 = smem_u32(sA), sw0 = smem_u32(sW);

    for (int kb = 0; kb < kd; kb += 64) {
        const int kg = kbase + kb;
        __syncthreads();
        for (int idx = t; idx < 64 * 8; idx += 256) {
            int r = idx >> 3, c = idx & 7;
            *(uint4*)(sA + r * AST + c * 8) =
                *(const uint4*)(A + (size_t)(row0 + r) * KDIM + kg + c * 8);
        }
        for (int idx = t; idx < 64 * 32; idx += 256) {
            int r = idx >> 5, c = idx & 31;
            *(uint4*)(sW + r * WST + c * 8) =
                *(const uint4*)(W + (size_t)(kg + r) * 256 + c * 8);
        }
        __syncthreads();
#pragma unroll
        for (int ks = 0; ks < 4; ks++) {
            uint32_t a[2][4];
#pragma unroll
            for (int mf = 0; mf < 2; mf++) {
                uint32_t off = (uint32_t)((wr * 32 + mf * 16 + aRow) * AST +
                                          ks * 16 + aCol) * 2;
                ldsm4(a[mf], sa0 + off);
            }
#pragma unroll
            for (int p = 0; p < 4; p++) {
                uint32_t bfr[4];
                uint32_t off = (uint32_t)((ks * 16 + aRow) * WST +
                                          wc * 64 + p * 16 + aCol) * 2;
                ldsm4t(bfr, sw0 + off);
#pragma unroll
                for (int mf = 0; mf < 2; mf++) {
                    mma_f16(acc[mf][p * 2 + 0], a[mf], &bfr[0]);
                    mma_f16(acc[mf][p * 2 + 1], a[mf], &bfr[2]);
                }
            }
        }
    }

#pragma unroll
    for (int mf = 0; mf < 2; mf++)
#pragma unroll
    for (int nf = 0; nf < 8; nf++)
#pragma unroll
    for (int pr = 0; pr < 2; pr++) {
        int r = row0 + wr * 32 + mf * 16 + (l >> 2) + pr * 8;
        int c = wc * 64 + nf * 8 + (l & 3) * 2;
        float v0 = acc[mf][nf][pr * 2 + 0];
        float v1 = acc[mf][nf][pr * 2 + 1];
        if (atomicF) {
            atomicAdd(outF + (size_t)r * 256 + c,     v0);
            atomicAdd(outF + (size_t)r * 256 + c + 1, v1);
        } else {
            v0 += bias[c]; v1 += bias[c + 1];
            if (outF) *(float2*)(outF + (size_t)r * 256 + c) = make_float2(v0, v1);
            *(uint32_t*)(outH + (size_t)r * 256 + c) =
                pack_h(__float2half_rn(v0), __float2half_rn(v1));
        }
    }
}

// ---------------------------------------------------------------------------
// gram (att2, fp16 MMA, blocks 0..63) + att3 Gram (fp32, blocks 64..79)
// ---------------------------------------------------------------------------
__global__ __launch_bounds__(256) void gram_att3_kernel(
    const __half* __restrict__ X2, float* __restrict__ att2,
    const float* __restrict__ X3, float* __restrict__ att3)
{
    constexpr int XST = 72;
    extern __shared__ char smbuf[];

    if (blockIdx.x < 64) {
        // ---- att2 gram: 128x128 tile ----
        __half* sI = (__half*)smbuf;
        __half* sJ = sI + 128 * XST;
        const int idx0 = blockIdx.x;
        const int b = idx0 >> 2;
        const int i0 = ((idx0 >> 1) & 1) * 128, j0 = (idx0 & 1) * 128;
        const int t = threadIdx.x, w = t >> 5, l = t & 31;
        const int wr = w >> 1, wc = w & 1;
        const int aRow = l & 15, aCol = (l >> 4) * 8;
        const int bRow = (l >> 4) * 8 + (l & 7), bCol = ((l >> 3) & 1) * 8;
        const __half* Xb = X2 + (size_t)b * 256 * CCH;

        float acc[2][8][4];
#pragma unroll
        for (int mf = 0; mf < 2; mf++)
#pragma unroll
            for (int nf = 0; nf < 8; nf++)
#pragma unroll
                for (int e = 0; e < 4; e++) acc[mf][nf][e] = 0.f;

        const uint32_t si0 = smem_u32(sI), sj0 = smem_u32(sJ);

        for (int kb = 0; kb < CCH; kb += 64) {
            __syncthreads();
            for (int idx = t; idx < 128 * 8; idx += 256) {
                int r = idx >> 3, c = idx & 7;
                *(uint4*)(sI + r * XST + c * 8) =
                    *(const uint4*)(Xb + (size_t)(i0 + r) * CCH + kb + c * 8);
                *(uint4*)(sJ + r * XST + c * 8) =
                    *(const uint4*)(Xb + (size_t)(j0 + r) * CCH + kb + c * 8);
            }
            __syncthreads();
#pragma unroll
            for (int ks = 0; ks < 4; ks++) {
                uint32_t a[2][4];
#pragma unroll
                for (int mf = 0; mf < 2; mf++) {
                    uint32_t off = (uint32_t)((wr * 32 + mf * 16 + aRow) * XST +
                                              ks * 16 + aCol) * 2;
                    ldsm4(a[mf], si0 + off);
                }
#pragma unroll
                for (int bt = 0; bt < 4; bt++) {
                    uint32_t bfr[4];
                    uint32_t off = (uint32_t)((wc * 64 + bt * 16 + bRow) * XST +
                                              ks * 16 + bCol) * 2;
                    ldsm4(bfr, sj0 + off);
#pragma unroll
                    for (int mf = 0; mf < 2; mf++) {
                        mma_f16(acc[mf][bt * 2 + 0], a[mf], &bfr[0]);
                        mma_f16(acc[mf][bt * 2 + 1], a[mf], &bfr[2]);
                    }
                }
            }
        }

#pragma unroll
        for (int mf = 0; mf < 2; mf++)
#pragma unroll
        for (int nf = 0; nf < 8; nf++)
#pragma unroll
        for (int pr = 0; pr < 2; pr++) {
            int i = i0 + wr * 32 + mf * 16 + (l >> 2) + pr * 8;
            int j = j0 + wc * 64 + nf * 8 + (l & 3) * 2;
            *(float2*)(att2 + (size_t)b * 256 * 256 + (size_t)i * 256 + j) =
                make_float2(acc[mf][nf][pr * 2 + 0], acc[mf][nf][pr * 2 + 1]);
        }
    } else {
        // ---- att3 gram: 64x64 fp32 ----
        float* Ai = (float*)smbuf;            // 32 x 65
        float* Bj = Ai + 32 * 65;
        const int b = blockIdx.x - 64;
        const int t = threadIdx.x;
        const int ty = t >> 4, tx = t & 15;
        const int r0 = ty * 4, c0 = tx * 4;
        const float* Xb = X3 + (size_t)b * 64 * CCH;

        float acc[4][4] = {};
        for (int k0 = 0; k0 < CCH; k0 += 32) {
            __syncthreads();
#pragma unroll
            for (int i = 0; i < 8; i++) {
                int lin = t + 256 * i;
                int r = lin >> 5, k = lin & 31;
                Ai[k * 65 + r] = Xb[(size_t)r * CCH + k0 + k];
            }
            __syncthreads();
#pragma unroll
            for (int k = 0; k < 32; k++) {
                float a[4], bb[4];
#pragma unroll
                for (int i = 0; i < 4; i++) a[i]  = Ai[k * 65 + r0 + i];
#pragma unroll
                for (int j = 0; j < 4; j++) bb[j] = Ai[k * 65 + c0 + j];
#pragma unroll
                for (int i = 0; i < 4; i++)
#pragma unroll
                    for (int j = 0; j < 4; j++)
                        acc[i][j] += a[i] * bb[j];
            }
        }
        (void)Bj;
#pragma unroll
        for (int i = 0; i < 4; i++) {
            float4 o = make_float4(acc[i][0], acc[i][1], acc[i][2], acc[i][3]);
            *(float4*)&att3[(size_t)b * 64 * 64 + (size_t)(r0 + i) * 64 + c0] = o;
        }
    }
}

// ---------------------------------------------------------------------------
// Fused sigmoid-attention (fp16), 2 CTAs/SM. m-tile 64 x 256 ch.
// 8 warps: wn = w&3 (16 n-rows), wc = w>>2 (m half / ch half).
// ---------------------------------------------------------------------------
#define KST 264
#define SST 72

__global__ __launch_bounds__(256, 2) void fused_mma_kernel(
    const __half* __restrict__ x1,
    const float* __restrict__ p1,
    const float* __restrict__ att2, const float* __restrict__ att3,
    const float* __restrict__ pa1, const float* __restrict__ pa2,
    const float* __restrict__ pa3, float* __restrict__ out)
{
    extern __shared__ char smbuf[];
    __half* Qs = (__half*)smbuf;            // 64 x 264
    __half* Ks = Qs + 64 * KST;             // 64 x 264
    __half* Ss = Ks + 64 * KST;             // 64 x 72
    float* A2s = (float*)(Ss + 64 * SST);   // 17 x 257
    float* A3s = A2s + 17 * 257;            // 5 x 65

    const int b  = blockIdx.y;
    const int n0 = blockIdx.x * 64;
    const int t  = threadIdx.x, w = t >> 5, l = t & 31;
    const int wn = w & 3, wc = w >> 2;
    const int aRow = l & 15, aCol = (l >> 4) * 8;
    const int bRow = (l >> 4) * 8 + (l & 7);
    const int bCol = ((l >> 3) & 1) * 8;

    const __half* Xb = x1 + (size_t)b * N1D * CCH;
    const float sa1 = *pa1, sa2 = *pa2, sa3 = *pa3;
    const int r2lo = n0 >> 2, r3lo = n0 >> 4;

#pragma unroll
    for (int i = 0; i < 8; i++) {
        int idx = t + 256 * i;
        int r = idx >> 5, c = idx & 31;
        *(uint4*)(Qs + r * KST + c * 8) =
            *(const uint4*)(Xb + (size_t)(n0 + r) * CCH + c * 8);
    }
    for (int i = t; i < 17 * 256; i += 256) {
        int rr = i >> 8, cc = i & 255;
        A2s[rr * 257 + cc] = att2[((size_t)b * 256 + min(r2lo + rr, 255)) * 256 + cc];
    }
    for (int i = t; i < 5 * 64; i += 256) {
        int rr = i >> 6, cc = i & 63;
        A3s[rr * 65 + cc] = att3[((size_t)b * 64 + min(r3lo + rr, 63)) * 64 + cc];
    }

    const uint32_t q0 = smem_u32(Qs);
    const uint32_t k0 = smem_u32(Ks);
    const uint32_t s0 = smem_u32(Ss);

    // per-thread row gating: int smem-offsets (register diet vs pointers)
    int o20[2], o21[2], o30[2], o31[2];
    float fnv[2], fn3v[2];
#pragma unroll
    for (int pr = 0; pr < 2; pr++) {
        int n = n0 + wn * 16 + (l >> 2) + pr * 8;
        int rn = n >> 2;
        fnv[pr] = (float)(n & 3) * 0.25f;
        o20[pr] = (rn - r2lo) * 257;
        o21[pr] = (min(rn + 1, 255) - r2lo) * 257;
        int rn3 = n >> 4;
        fn3v[pr] = (float)(n & 15) * 0.0625f;
        o30[pr] = (rn3 - r3lo) * 65;
        o31[pr] = (min(rn3 + 1, 63) - r3lo) * 65;
    }

    float O[16][4];
#pragma unroll
    for (int f = 0; f < 16; f++)
#pragma unroll
        for (int e = 0; e < 4; e++) O[f][e] = 0.f;

    for (int mt = 0; mt < 16; mt++) {
        const int m0 = mt * 64;
        __syncthreads();
#pragma unroll
        for (int i = 0; i < 8; i++) {
            int idx = t + 256 * i;
            int r = idx >> 5, c = idx & 31;
            *(uint4*)(Ks + r * KST + c * 8) =
                *(const uint4*)(Xb + (size_t)(m0 + r) * CCH + c * 8);
        }
        __syncthreads();

        // ---- GEMM1: S(64x64) = Q . K^T ----
        float Sa[4][4];
#pragma unroll
        for (int nf = 0; nf < 4; nf++)
#pragma unroll
            for (int e = 0; e < 4; e++) Sa[nf][e] = 0.f;

#pragma unroll
        for (int kc = 0; kc < 16; kc++) {
            uint32_t a[4];
            uint32_t offA = (uint32_t)((wn * 16 + aRow) * KST + kc * 16 + aCol) * 2;
            ldsm4(a, q0 + offA);
#pragma unroll
            for (int bt = 0; bt < 2; bt++) {
                uint32_t r[4];
                uint32_t offB = (uint32_t)((wc * 32 + bt * 16 + bRow) * KST +
                                           kc * 16 + bCol) * 2;
                ldsm4(r, k0 + offB);
                mma_f16(Sa[bt * 2 + 0], a, &r[0]);
                mma_f16(Sa[bt * 2 + 1], a, &r[2]);
            }
        }

        // ---- epilogue: gating + sigmoid -> Ss ----
#pragma unroll
        for (int nf = 0; nf < 4; nf++)
#pragma unroll
        for (int pr = 0; pr < 2; pr++) {
            const int row_l = wn * 16 + (l >> 2) + pr * 8;
            const int col_l = wc * 32 + nf * 8 + (l & 3) * 2;
            const float fn = fnv[pr], fn3 = fn3v[pr];
            const float *R0 = A2s + o20[pr], *R1 = A2s + o21[pr];
            const float *T0 = A3s + o30[pr], *T1 = A3s + o31[pr];
            __half hv[2];
#pragma unroll
            for (int e = 0; e < 2; e++) {
                int m = m0 + col_l + e;
                float Sv = Sa[nf][pr * 2 + e];
                int cm = m >> 2;
                float fm = (float)(m & 3) * 0.25f;
                int cm1 = min(cm + 1, 255);
                float v2 = (1.f - fn) * ((1.f - fm) * R0[cm] + fm * R0[cm1]) +
                           fn         * ((1.f - fm) * R1[cm] + fm * R1[cm1]);
                int cm3 = m >> 4;
                float fm3 = (float)(m & 15) * 0.0625f;
                int cm31 = min(cm3 + 1, 63);
                float v3 = (1.f - fn3) * ((1.f - fm3) * T0[cm3] + fm3 * T0[cm31]) +
                           fn3         * ((1.f - fm3) * T1[cm3] + fm3 * T1[cm31]);
                float val = sa1 * Sv + sa2 * v2 + sa3 * v3;
                float sg = 1.0f / (1.0f + __expf(-val));
                hv[e] = __float2half_rn(sg);
            }
            *(uint32_t*)&Ss[row_l * SST + col_l] = pack_h(hv[0], hv[1]);
        }
        __syncthreads();

        // ---- GEMM2: O(64x256) += S(64x64) . K(64x256) ----
#pragma unroll
        for (int kc = 0; kc < 4; kc++) {
            uint32_t sA[4];
            uint32_t offA = (uint32_t)((wn * 16 + aRow) * SST + kc * 16 + aCol) * 2;
            ldsm4(sA, s0 + offA);
#pragma unroll
            for (int p = 0; p < 8; p++) {
                uint32_t r[4];
                uint32_t offB = (uint32_t)((kc * 16 + aRow) * KST +
                                           wc * 128 + p * 16 + aCol) * 2;
                ldsm4t(r, k0 + offB);
                mma_f16(O[p * 2 + 0], sA, &r[0]);
                mma_f16(O[p * 2 + 1], sA, &r[2]);
            }
        }
    }

    // ---- final: out = O + p1 ----
#pragma unroll
    for (int f = 0; f < 16; f++)
#pragma unroll
    for (int pr = 0; pr < 2; pr++) {
        const int n  = n0 + wn * 16 + (l >> 2) + pr * 8;
        const int ch = wc * 128 + f * 8 + (l & 3) * 2;
        const size_t o = ((size_t)(b * N1D + n)) * CCH + ch;
        float2 pv = *(const float2*)(p1 + o);
        *(float2*)(out + o) = make_float2(O[f][pr * 2 + 0] + pv.x,
                                          O[f][pr * 2 + 1] + pv.y);
    }
}

// ---------------------------------------------------------------------------
extern "C" void kernel_launch(void* const* d_in, const int* in_sizes, int n_in,
                              void* d_out, int out_size)
{
    const float* f1 = (const float*)d_in[0];
    const float* f2 = (const float*)d_in[1];
    const float* f3 = (const float*)d_in[2];
    const float* w1 = (const float*)d_in[3];
    const float* b1 = (const float*)d_in[4];
    const float* w2 = (const float*)d_in[5];
    const float* b2 = (const float*)d_in[6];
    const float* w3 = (const float*)d_in[7];
    const float* b3 = (const float*)d_in[8];
    const float* a1 = (const float*)d_in[9];
    const float* a2 = (const float*)d_in[10];
    const float* a3 = (const float*)d_in[11];
    float* out = (float*)d_out;

    float *p1, *x3, *att2, *att3;
    __half *x1, *x2, *hf1, *hf2, *hf3, *hw1, *hw2, *hw3;
    cudaGetSymbolAddress((void**)&p1,   g_p1);
    cudaGetSymbolAddress((void**)&x3,   g_x3);
    cudaGetSymbolAddress((void**)&att2, g_att2);
    cudaGetSymbolAddress((void**)&att3, g_att3);
    cudaGetSymbolAddress((void**)&x1,   g_x1);
    cudaGetSymbolAddress((void**)&x2,   g_x2);
    cudaGetSymbolAddress((void**)&hf1,  g_f1);
    cudaGetSymbolAddress((void**)&hf2,  g_f2);
    cudaGetSymbolAddress((void**)&hf3,  g_f3);
    cudaGetSymbolAddress((void**)&hw1,  g_w1);
    cudaGetSymbolAddress((void**)&hw2,  g_w2);
    cudaGetSymbolAddress((void**)&hw3,  g_w3);

    // 1) convert inputs + init x3 with bias (one launch)
    cvt_all_kernel<<<7872, 256>>>(f1, f2, f3, w1, w2, w3, b3,
                                  hf1, hf2, hf3, hw1, hw2, hw3, x3);

    // 2) all projections (one launch, 384 CTAs)
    const int smemP = (64 * 72 + 64 * 264) * 2;
    cudaFuncSetAttribute(projall_kernel,
                         cudaFuncAttributeMaxDynamicSharedMemorySize, smemP);
    projall_kernel<<<384, 256, smemP>>>(hf1, hw1, b1, p1, x1,
                                        hf2, hw2, b2, x2,
                                        hf3, hw3, x3);

    // 3) gram att2 + gram att3 (one launch, 80 CTAs)
    const int smemG = 2 * 128 * 72 * 2;
    cudaFuncSetAttribute(gram_att3_kernel,
                         cudaFuncAttributeMaxDynamicSharedMemorySize, smemG);
    gram_att3_kernel<<<80, 256, smemG>>>(x2, att2, x3, att3);

    // 4) fused attention (2 CTAs/SM)
    const int smemF = (64 * KST + 64 * KST + 64 * SST) * 2
                      + (17 * 257 + 5 * 65) * 4;
    cudaFuncSetAttribute(fused_mma_kernel,
                         cudaFuncAttributeMaxDynamicSharedMemorySize, smemF);
    fused_mma_kernel<<<dim3(16, BATCH), 256, smemF>>>(
        x1, p1, att2, att3, a1, a2, a3, out);
}